// round 1
// baseline (speedup 1.0000x reference)
#include <cuda_runtime.h>
#include <math.h>

#define M_DIM 1024
#define N_DIM 4096
#define D_DIM 128
#define H_DIM 32
#define P_POS 2048
#define L_DIM 4096

// Scratch for projected Q/K/V, each [M, N] row-major (col = h*128 + d).
__device__ float g_Q[M_DIM * (size_t)N_DIM];
__device__ float g_K[M_DIM * (size_t)N_DIM];
__device__ float g_V[M_DIM * (size_t)N_DIM];

// ---------------------------------------------------------------------------
// QKV projection: C = X[1024,4096] @ W[4096,4096], z selects {Wq,Wk,Wv}.
// 128x128x16 block tile, 8x8 micro-tile, 256 threads.
// ---------------------------------------------------------------------------
#define GBM 128
#define GBN 128
#define GBK 16

__global__ __launch_bounds__(256) void qkv_gemm_kernel(
    const float* __restrict__ X,
    const float* __restrict__ Wq,
    const float* __restrict__ Wk,
    const float* __restrict__ Wv)
{
    const float* B = (blockIdx.z == 0) ? Wq : (blockIdx.z == 1) ? Wk : Wv;
    float* C = (blockIdx.z == 0) ? g_Q : (blockIdx.z == 1) ? g_K : g_V;

    __shared__ float As[GBK][GBM];
    __shared__ float Bs[GBK][GBN];

    const int tid = threadIdx.x;
    const int tx = tid & 15;
    const int ty = tid >> 4;
    const int row0 = blockIdx.y * GBM;
    const int col0 = blockIdx.x * GBN;

    float acc[8][8];
#pragma unroll
    for (int i = 0; i < 8; i++)
#pragma unroll
        for (int j = 0; j < 8; j++) acc[i][j] = 0.0f;

    for (int k0 = 0; k0 < N_DIM; k0 += GBK) {
#pragma unroll
        for (int i = 0; i < 2; i++) {
            int idx = tid * 2 + i;
            // A tile: 128 rows x 16 k, transposed store
            int ar = idx >> 2;
            int ak = (idx & 3) * 4;
            float4 a = *(const float4*)&X[(size_t)(row0 + ar) * N_DIM + k0 + ak];
            As[ak + 0][ar] = a.x;
            As[ak + 1][ar] = a.y;
            As[ak + 2][ar] = a.z;
            As[ak + 3][ar] = a.w;
            // B tile: 16 rows x 128 cols, direct
            int bk = idx >> 5;
            int bn = (idx & 31) * 4;
            *(float4*)&Bs[bk][bn] =
                *(const float4*)&B[(size_t)(k0 + bk) * N_DIM + col0 + bn];
        }
        __syncthreads();
#pragma unroll
        for (int k = 0; k < GBK; k++) {
            float ra[8], rb[8];
            *(float4*)&ra[0] = *(float4*)&As[k][ty * 8];
            *(float4*)&ra[4] = *(float4*)&As[k][ty * 8 + 4];
            *(float4*)&rb[0] = *(float4*)&Bs[k][tx * 8];
            *(float4*)&rb[4] = *(float4*)&Bs[k][tx * 8 + 4];
#pragma unroll
            for (int i = 0; i < 8; i++)
#pragma unroll
                for (int j = 0; j < 8; j++)
                    acc[i][j] += ra[i] * rb[j];
        }
        __syncthreads();
    }

#pragma unroll
    for (int i = 0; i < 8; i++) {
        int r = row0 + ty * 8 + i;
#pragma unroll
        for (int j4 = 0; j4 < 2; j4++) {
            float4 v = make_float4(acc[i][j4 * 4 + 0], acc[i][j4 * 4 + 1],
                                   acc[i][j4 * 4 + 2], acc[i][j4 * 4 + 3]);
            *(float4*)&C[(size_t)r * N_DIM + col0 + tx * 8 + j4 * 4] = v;
        }
    }
}

// ---------------------------------------------------------------------------
// Attention: per block = (64 q-rows, 1 head). Stream over L in 64-chunks.
// Naive exp softmax (matches reference: no max subtraction), so we can
// accumulate unnormalized O and the row-sum and divide at the end.
// Fresh KV rows [P, P+M) are read from g_K/g_V instead of the cache.
// SMEM: Qs[128][64] (swizzled T), KVs shared K-T/V buffer, Ps[64][68].
// ---------------------------------------------------------------------------
#define AT_BM 64
#define AT_BL 64
#define AT_PS_LD 68
#define AT_SMEM_FLOATS (D_DIM * AT_BM + AT_BL * D_DIM + AT_BL * AT_PS_LD + AT_BM)
#define AT_SMEM_BYTES (AT_SMEM_FLOATS * 4)

__global__ __launch_bounds__(256) void attn_kernel(
    const float* __restrict__ cacheK,
    const float* __restrict__ cacheV,
    float* __restrict__ out)
{
    extern __shared__ float smem[];
    float* Qs = smem;                            // [128][64] swizzled transpose
    float* KVs = Qs + D_DIM * AT_BM;             // K: [128][64] swz-T ; V: [64][128]
    float* Ps = KVs + AT_BL * D_DIM;             // [64 l][68] (exp weights, l-major)
    float* rsum_s = Ps + AT_BL * AT_PS_LD;       // [64]

    const int mb = blockIdx.x;
    const int h = blockIdx.y;
    const int m0 = mb * AT_BM;
    const int tid = threadIdx.x;
    const int tx = tid & 15;
    const int ty = tid >> 4;

    // Load Q tile, transposed with 16-granule XOR swizzle (conflict-free reads).
#pragma unroll
    for (int i = 0; i < 8; i++) {
        int idx = tid + i * 256;
        int m = idx >> 5;
        int d0 = (idx & 31) * 4;
        float4 q = *(const float4*)&g_Q[(size_t)(m0 + m) * N_DIM + h * D_DIM + d0];
        int g = ((((m >> 2) ^ ((d0 >> 2) & 15)) << 2) | (m & 3));
        Qs[(d0 + 0) * AT_BM + g] = q.x;
        Qs[(d0 + 1) * AT_BM + g] = q.y;
        Qs[(d0 + 2) * AT_BM + g] = q.z;
        Qs[(d0 + 3) * AT_BM + g] = q.w;
    }

    float accO[4][8];
#pragma unroll
    for (int i = 0; i < 4; i++)
#pragma unroll
        for (int j = 0; j < 8; j++) accO[i][j] = 0.0f;
    float rsum[4] = {0.0f, 0.0f, 0.0f, 0.0f};

    for (int l0 = 0; l0 < L_DIM; l0 += AT_BL) {
        const bool fresh = (l0 >= P_POS) && (l0 < P_POS + M_DIM);
        __syncthreads();  // prev chunk's PV reads of KVs/Ps are done

        // K chunk -> swizzled transpose
#pragma unroll
        for (int i = 0; i < 8; i++) {
            int idx = tid + i * 256;
            int l = idx >> 5;
            int d0 = (idx & 31) * 4;
            float4 kq;
            if (fresh)
                kq = *(const float4*)&g_K[(size_t)(l0 + l - P_POS) * N_DIM + h * D_DIM + d0];
            else
                kq = *(const float4*)&cacheK[((size_t)h * L_DIM + l0 + l) * D_DIM + d0];
            int g = ((((l >> 2) ^ ((d0 >> 2) & 15)) << 2) | (l & 3));
            KVs[(d0 + 0) * AT_BL + g] = kq.x;
            KVs[(d0 + 1) * AT_BL + g] = kq.y;
            KVs[(d0 + 2) * AT_BL + g] = kq.z;
            KVs[(d0 + 3) * AT_BL + g] = kq.w;
        }
        __syncthreads();

        // S = Q @ K^T  (64x64 over d=128), 4x4 per thread
        float accS[4][4];
#pragma unroll
        for (int i = 0; i < 4; i++)
#pragma unroll
            for (int j = 0; j < 4; j++) accS[i][j] = 0.0f;
#pragma unroll 4
        for (int d = 0; d < D_DIM; d++) {
            int s = (d >> 2) & 15;
            float ra[4], rb[4];
            *(float4*)ra = *(float4*)&Qs[d * AT_BM + ((ty ^ s) << 2)];
            *(float4*)rb = *(float4*)&KVs[d * AT_BL + ((tx ^ s) << 2)];
#pragma unroll
            for (int i = 0; i < 4; i++)
#pragma unroll
                for (int j = 0; j < 4; j++)
                    accS[i][j] += ra[i] * rb[j];
        }

        // exp -> Ps (l-major) and row-sum partials
#pragma unroll
        for (int j = 0; j < 4; j++)
#pragma unroll
            for (int i = 0; i < 4; i++) {
                float e = expf(accS[i][j]);
                Ps[(tx * 4 + j) * AT_PS_LD + ty * 4 + i] = e;
                rsum[i] += e;
            }
        __syncthreads();  // Ps written, K no longer needed

        // V chunk -> row-major in same buffer
#pragma unroll
        for (int i = 0; i < 8; i++) {
            int idx = tid + i * 256;
            int l = idx >> 5;
            int d0 = (idx & 31) * 4;
            float4 v;
            if (fresh)
                v = *(const float4*)&g_V[(size_t)(l0 + l - P_POS) * N_DIM + h * D_DIM + d0];
            else
                v = *(const float4*)&cacheV[((size_t)h * L_DIM + l0 + l) * D_DIM + d0];
            *(float4*)&KVs[l * D_DIM + d0] = v;
        }
        __syncthreads();

        // O += P @ V  (64x128 over l=64), 4x8 per thread (same rows as S)
#pragma unroll 2
        for (int l = 0; l < AT_BL; l++) {
            float rp[4], rv[8];
            *(float4*)rp = *(float4*)&Ps[l * AT_PS_LD + ty * 4];
            *(float4*)&rv[0] = *(float4*)&KVs[l * D_DIM + tx * 8];
            *(float4*)&rv[4] = *(float4*)&KVs[l * D_DIM + tx * 8 + 4];
#pragma unroll
            for (int i = 0; i < 4; i++)
#pragma unroll
                for (int j = 0; j < 8; j++)
                    accO[i][j] += rp[i] * rv[j];
        }
    }

    // Reduce rsum over tx (lanes 0..15 within each half-warp)
#pragma unroll
    for (int i = 0; i < 4; i++) {
        float s = rsum[i];
        s += __shfl_xor_sync(0xffffffffu, s, 1);
        s += __shfl_xor_sync(0xffffffffu, s, 2);
        s += __shfl_xor_sync(0xffffffffu, s, 4);
        s += __shfl_xor_sync(0xffffffffu, s, 8);
        if (tx == 0) rsum_s[ty * 4 + i] = s;
    }
    __syncthreads();

#pragma unroll
    for (int i = 0; i < 4; i++) {
        float inv = 1.0f / rsum_s[ty * 4 + i];
        int m = m0 + ty * 4 + i;
        float4 o0 = make_float4(accO[i][0] * inv, accO[i][1] * inv,
                                accO[i][2] * inv, accO[i][3] * inv);
        float4 o1 = make_float4(accO[i][4] * inv, accO[i][5] * inv,
                                accO[i][6] * inv, accO[i][7] * inv);
        *(float4*)&out[(size_t)m * N_DIM + h * D_DIM + tx * 8] = o0;
        *(float4*)&out[(size_t)m * N_DIM + h * D_DIM + tx * 8 + 4] = o1;
    }
}

// ---------------------------------------------------------------------------
extern "C" void kernel_launch(void* const* d_in, const int* in_sizes, int n_in,
                              void* d_out, int out_size)
{
    const float* X = (const float*)d_in[0];
    const float* Wq = (const float*)d_in[1];
    const float* Wk = (const float*)d_in[2];
    const float* Wv = (const float*)d_in[3];
    const float* cK = (const float*)d_in[4];
    const float* cV = (const float*)d_in[5];
    float* out = (float*)d_out;

    dim3 gemm_grid(N_DIM / GBN, M_DIM / GBM, 3);
    qkv_gemm_kernel<<<gemm_grid, 256>>>(X, Wq, Wk, Wv);

    // Idempotent, non-stream API: safe under graph capture.
    cudaFuncSetAttribute(attn_kernel, cudaFuncAttributeMaxDynamicSharedMemorySize,
                         AT_SMEM_BYTES);
    dim3 attn_grid(M_DIM / AT_BM, H_DIM);
    attn_kernel<<<attn_grid, 256, AT_SMEM_BYTES>>>(cK, cV, out);
}

// round 2
// speedup vs baseline: 3.1682x; 3.1682x over previous
#include <cuda_runtime.h>
#include <math.h>
#include <stdint.h>

#define M_DIM 1024
#define N_DIM 4096
#define D_DIM 128
#define H_DIM 32
#define P_POS 2048
#define L_DIM 4096

// Scratch for projected Q/K/V, each [M, N] row-major (col = h*128 + d).
__device__ float g_Q[M_DIM * (size_t)N_DIM];
__device__ float g_K[M_DIM * (size_t)N_DIM];
__device__ float g_V[M_DIM * (size_t)N_DIM];

// ---------------------------------------------------------------------------
// helpers
// ---------------------------------------------------------------------------
__device__ __forceinline__ uint32_t f2tf(float f) {
    uint32_t u;
    asm("cvt.rna.tf32.f32 %0, %1;" : "=r"(u) : "f"(f));
    return u;
}

__device__ __forceinline__ void mma_tf32(float* c, const uint32_t* a, const uint32_t* b) {
    asm volatile(
        "mma.sync.aligned.m16n8k8.row.col.f32.tf32.tf32.f32 "
        "{%0,%1,%2,%3},{%4,%5,%6,%7},{%8,%9},{%0,%1,%2,%3};"
        : "+f"(c[0]), "+f"(c[1]), "+f"(c[2]), "+f"(c[3])
        : "r"(a[0]), "r"(a[1]), "r"(a[2]), "r"(a[3]), "r"(b[0]), "r"(b[1]));
}

__device__ __forceinline__ void cp16(float* s, const float* g) {
    uint32_t sa = (uint32_t)__cvta_generic_to_shared(s);
    asm volatile("cp.async.cg.shared.global [%0], [%1], 16;" :: "r"(sa), "l"(g));
}
#define CP_COMMIT asm volatile("cp.async.commit_group;")
#define CP_WAIT0  asm volatile("cp.async.wait_group 0;")

// ---------------------------------------------------------------------------
// QKV projection: C = X[1024,4096] @ W[4096,4096], z selects {Wq,Wk,Wv}.
// CTA tile 128x128, k-chunk 32, tf32 mma, cp.async double buffer.
// ---------------------------------------------------------------------------
#define A_LD 36
#define B_LD 136
#define GEMM_BUF (128 * A_LD + 32 * B_LD)   // floats per buffer
#define GEMM_SMEM (2 * GEMM_BUF * 4)        // bytes

__global__ __launch_bounds__(256, 2) void qkv_gemm_kernel(
    const float* __restrict__ X,
    const float* __restrict__ Wq,
    const float* __restrict__ Wk,
    const float* __restrict__ Wv)
{
    extern __shared__ float sm[];
    const float* W = (blockIdx.z == 0) ? Wq : (blockIdx.z == 1) ? Wk : Wv;
    float* C = (blockIdx.z == 0) ? g_Q : (blockIdx.z == 1) ? g_K : g_V;

    const int tid = threadIdx.x;
    const int lane = tid & 31;
    const int wid = tid >> 5;
    const int wm = wid & 1;     // 2 warps over M -> 64 rows each
    const int wn = wid >> 1;    // 4 warps over N -> 32 cols each
    const int row0 = blockIdx.y * 128;
    const int col0 = blockIdx.x * 128;

    float acc[4][4][4];
#pragma unroll
    for (int i = 0; i < 4; i++)
#pragma unroll
        for (int j = 0; j < 4; j++)
#pragma unroll
            for (int e = 0; e < 4; e++) acc[i][j][e] = 0.0f;

    // prefetch chunk 0
    {
        float* As = sm;
        float* Bs = sm + 128 * A_LD;
#pragma unroll
        for (int i = 0; i < 4; i++) {
            int idx = tid + i * 256;
            int r = idx >> 3, c4 = idx & 7;
            cp16(&As[r * A_LD + c4 * 4], &X[(size_t)(row0 + r) * N_DIM + c4 * 4]);
        }
#pragma unroll
        for (int i = 0; i < 4; i++) {
            int idx = tid + i * 256;
            int r = idx >> 5, c4 = idx & 31;
            cp16(&Bs[r * B_LD + c4 * 4], &W[(size_t)r * N_DIM + col0 + c4 * 4]);
        }
        CP_COMMIT;
    }

    int buf = 0;
    for (int kc = 0; kc < N_DIM / 32; kc++) {
        CP_WAIT0;
        __syncthreads();
        if (kc + 1 < N_DIM / 32) {
            int k0 = (kc + 1) * 32;
            float* As = sm + (buf ^ 1) * GEMM_BUF;
            float* Bs = As + 128 * A_LD;
#pragma unroll
            for (int i = 0; i < 4; i++) {
                int idx = tid + i * 256;
                int r = idx >> 3, c4 = idx & 7;
                cp16(&As[r * A_LD + c4 * 4], &X[(size_t)(row0 + r) * N_DIM + k0 + c4 * 4]);
            }
#pragma unroll
            for (int i = 0; i < 4; i++) {
                int idx = tid + i * 256;
                int r = idx >> 5, c4 = idx & 31;
                cp16(&Bs[r * B_LD + c4 * 4], &W[(size_t)(k0 + r) * N_DIM + col0 + c4 * 4]);
            }
            CP_COMMIT;
        }

        const float* As = sm + buf * GEMM_BUF;
        const float* Bs = As + 128 * A_LD;
#pragma unroll
        for (int k8 = 0; k8 < 4; k8++) {
            const int kb = k8 * 8;
            uint32_t af[4][4];
#pragma unroll
            for (int mt = 0; mt < 4; mt++) {
                int r = wm * 64 + mt * 16 + (lane >> 2);
                int c = kb + (lane & 3);
                af[mt][0] = f2tf(As[r * A_LD + c]);
                af[mt][1] = f2tf(As[(r + 8) * A_LD + c]);
                af[mt][2] = f2tf(As[r * A_LD + c + 4]);
                af[mt][3] = f2tf(As[(r + 8) * A_LD + c + 4]);
            }
            uint32_t bf[4][2];
#pragma unroll
            for (int nt = 0; nt < 4; nt++) {
                int cc = wn * 32 + nt * 8 + (lane >> 2);
                int rk = kb + (lane & 3);
                bf[nt][0] = f2tf(Bs[rk * B_LD + cc]);
                bf[nt][1] = f2tf(Bs[(rk + 4) * B_LD + cc]);
            }
#pragma unroll
            for (int mt = 0; mt < 4; mt++)
#pragma unroll
                for (int nt = 0; nt < 4; nt++)
                    mma_tf32(acc[mt][nt], af[mt], bf[nt]);
        }
        buf ^= 1;
    }

    // epilogue
#pragma unroll
    for (int mt = 0; mt < 4; mt++) {
#pragma unroll
        for (int nt = 0; nt < 4; nt++) {
            int r = row0 + wm * 64 + mt * 16 + (lane >> 2);
            int c = col0 + wn * 32 + nt * 8 + 2 * (lane & 3);
            float2 v0 = make_float2(acc[mt][nt][0], acc[mt][nt][1]);
            float2 v1 = make_float2(acc[mt][nt][2], acc[mt][nt][3]);
            *(float2*)&C[(size_t)r * N_DIM + c] = v0;
            *(float2*)&C[(size_t)(r + 8) * N_DIM + c] = v1;
        }
    }
}

// ---------------------------------------------------------------------------
// Attention with tf32 mma: per CTA = (64 q-rows, 1 head). Chunks of 64 l.
// Naive exp softmax (matches reference): unnormalized O + row-sum, divide at end.
// Fresh rows [P, P+M) read from g_K/g_V.
// ---------------------------------------------------------------------------
#define AT_BM 64
#define AT_BL 64
#define KV_LD 132
#define PS_LD 68
// smem floats: Qs + KVs(shared K/V) + Ps + rsum_s[64][4] + rtot[64]
#define AT_SMEM_FLOATS (AT_BM * KV_LD + AT_BL * KV_LD + AT_BM * PS_LD + 64 * 4 + 64)
#define AT_SMEM_BYTES (AT_SMEM_FLOATS * 4)

__global__ __launch_bounds__(256, 2) void attn_kernel(
    const float* __restrict__ cacheK,
    const float* __restrict__ cacheV,
    float* __restrict__ out)
{
    extern __shared__ float sm[];
    float* Qs = sm;                        // [64][132] raw fp32, row-major (m,d)
    float* KVs = Qs + AT_BM * KV_LD;       // [64][132] raw fp32, row-major (l,d)
    float* Ps = KVs + AT_BL * KV_LD;       // [64][68]  tf32 bits (m,l)
    float* rsum_s = Ps + AT_BM * PS_LD;    // [64][4]
    float* rtot = rsum_s + 64 * 4;         // [64] : 1/sum

    const int tid = threadIdx.x;
    const int lane = tid & 31;
    const int wid = tid >> 5;
    const int wm = wid & 1;    // 2 warps over M (32 rows each)
    const int wn = wid >> 1;   // 4 warps over N
    const int m0 = blockIdx.x * AT_BM;
    const int h = blockIdx.y;

    // load Q tile (coalesced float4)
#pragma unroll
    for (int i = 0; i < 8; i++) {
        int idx = tid + i * 256;
        int m = idx >> 5;
        int d0 = (idx & 31) * 4;
        float4 q = *(const float4*)&g_Q[(size_t)(m0 + m) * N_DIM + h * D_DIM + d0];
        *(float4*)&Qs[m * KV_LD + d0] = q;
    }

    float accO[2][4][4];
#pragma unroll
    for (int i = 0; i < 2; i++)
#pragma unroll
        for (int j = 0; j < 4; j++)
#pragma unroll
            for (int e = 0; e < 4; e++) accO[i][j][e] = 0.0f;
    float rs[2][2] = {{0.f, 0.f}, {0.f, 0.f}};

    for (int l0 = 0; l0 < L_DIM; l0 += AT_BL) {
        const bool fresh = (l0 >= P_POS) && (l0 < P_POS + M_DIM);
        __syncthreads();  // prev chunk PV done with KVs/Ps

        // K chunk -> KVs [l][d], coalesced
#pragma unroll
        for (int i = 0; i < 8; i++) {
            int idx = tid + i * 256;
            int l = idx >> 5;
            int d0 = (idx & 31) * 4;
            float4 kq = fresh
                ? *(const float4*)&g_K[(size_t)(l0 + l - P_POS) * N_DIM + h * D_DIM + d0]
                : *(const float4*)&cacheK[((size_t)h * L_DIM + l0 + l) * D_DIM + d0];
            *(float4*)&KVs[l * KV_LD + d0] = kq;
        }
        __syncthreads();

        // S = Q @ K^T : M=64, N=64, K=128. warp tile 32x16 (2x2 mma tiles)
        float accS[2][2][4];
#pragma unroll
        for (int i = 0; i < 2; i++)
#pragma unroll
            for (int j = 0; j < 2; j++)
#pragma unroll
                for (int e = 0; e < 4; e++) accS[i][j][e] = 0.0f;

#pragma unroll
        for (int k8 = 0; k8 < 16; k8++) {
            const int kb = k8 * 8;
            uint32_t af[2][4];
#pragma unroll
            for (int mt = 0; mt < 2; mt++) {
                int r = wm * 32 + mt * 16 + (lane >> 2);
                int c = kb + (lane & 3);
                af[mt][0] = f2tf(Qs[r * KV_LD + c]);
                af[mt][1] = f2tf(Qs[(r + 8) * KV_LD + c]);
                af[mt][2] = f2tf(Qs[r * KV_LD + c + 4]);
                af[mt][3] = f2tf(Qs[(r + 8) * KV_LD + c + 4]);
            }
            uint32_t bf[2][2];
#pragma unroll
            for (int nt = 0; nt < 2; nt++) {
                int ln = wn * 16 + nt * 8 + (lane >> 2);
                int d = kb + (lane & 3);
                bf[nt][0] = f2tf(KVs[ln * KV_LD + d]);
                bf[nt][1] = f2tf(KVs[ln * KV_LD + d + 4]);
            }
#pragma unroll
            for (int mt = 0; mt < 2; mt++)
#pragma unroll
                for (int nt = 0; nt < 2; nt++)
                    mma_tf32(accS[mt][nt], af[mt], bf[nt]);
        }

        // exp -> Ps (tf32 bits), accumulate row sums
#pragma unroll
        for (int mt = 0; mt < 2; mt++)
#pragma unroll
            for (int nt = 0; nt < 2; nt++)
#pragma unroll
                for (int e = 0; e < 4; e++) {
                    float ev = __expf(accS[mt][nt][e]);
                    int row = wm * 32 + mt * 16 + (lane >> 2) + (e >> 1) * 8;
                    int col = wn * 16 + nt * 8 + 2 * (lane & 3) + (e & 1);
                    Ps[row * PS_LD + col] = __uint_as_float(f2tf(ev));
                    rs[mt][e >> 1] += ev;
                }
        __syncthreads();  // all S/Ps done; KVs free for V

        // V chunk -> KVs [l][d]
#pragma unroll
        for (int i = 0; i < 8; i++) {
            int idx = tid + i * 256;
            int l = idx >> 5;
            int d0 = (idx & 31) * 4;
            float4 v = fresh
                ? *(const float4*)&g_V[(size_t)(l0 + l - P_POS) * N_DIM + h * D_DIM + d0]
                : *(const float4*)&cacheV[((size_t)h * L_DIM + l0 + l) * D_DIM + d0];
            *(float4*)&KVs[l * KV_LD + d0] = v;
        }
        __syncthreads();

        // O += P @ V : M=64, N=128, K=64. warp tile 32x32 (2x4 mma tiles)
#pragma unroll
        for (int k8 = 0; k8 < 8; k8++) {
            const int kb = k8 * 8;
            uint32_t af[2][4];
#pragma unroll
            for (int mt = 0; mt < 2; mt++) {
                int r = wm * 32 + mt * 16 + (lane >> 2);
                int c = kb + (lane & 3);
                af[mt][0] = __float_as_uint(Ps[r * PS_LD + c]);
                af[mt][1] = __float_as_uint(Ps[(r + 8) * PS_LD + c]);
                af[mt][2] = __float_as_uint(Ps[r * PS_LD + c + 4]);
                af[mt][3] = __float_as_uint(Ps[(r + 8) * PS_LD + c + 4]);
            }
            uint32_t bf[4][2];
#pragma unroll
            for (int nt = 0; nt < 4; nt++) {
                int d = wn * 32 + nt * 8 + (lane >> 2);
                int l = kb + (lane & 3);
                bf[nt][0] = f2tf(KVs[l * KV_LD + d]);
                bf[nt][1] = f2tf(KVs[(l + 4) * KV_LD + d]);
            }
#pragma unroll
            for (int mt = 0; mt < 2; mt++)
#pragma unroll
                for (int nt = 0; nt < 4; nt++)
                    mma_tf32(accO[mt][nt], af[mt], bf[nt]);
        }
    }

    // reduce row sums: lanes sharing a row are those with equal lane>>2
#pragma unroll
    for (int mt = 0; mt < 2; mt++)
#pragma unroll
        for (int hh = 0; hh < 2; hh++) {
            float s = rs[mt][hh];
            s += __shfl_xor_sync(0xffffffffu, s, 1);
            s += __shfl_xor_sync(0xffffffffu, s, 2);
            if ((lane & 3) == 0) {
                int row = wm * 32 + mt * 16 + hh * 8 + (lane >> 2);
                rsum_s[row * 4 + wn] = s;
            }
        }
    __syncthreads();
    if (tid < 64) {
        float s = rsum_s[tid * 4 + 0] + rsum_s[tid * 4 + 1] +
                  rsum_s[tid * 4 + 2] + rsum_s[tid * 4 + 3];
        rtot[tid] = 1.0f / s;
    }
    __syncthreads();

    // write O
#pragma unroll
    for (int mt = 0; mt < 2; mt++) {
        int rbase = wm * 32 + mt * 16 + (lane >> 2);
        float inv0 = rtot[rbase];
        float inv1 = rtot[rbase + 8];
#pragma unroll
        for (int nt = 0; nt < 4; nt++) {
            int d = wn * 32 + nt * 8 + 2 * (lane & 3);
            float2 v0 = make_float2(accO[mt][nt][0] * inv0, accO[mt][nt][1] * inv0);
            float2 v1 = make_float2(accO[mt][nt][2] * inv1, accO[mt][nt][3] * inv1);
            *(float2*)&out[(size_t)(m0 + rbase) * N_DIM + h * D_DIM + d] = v0;
            *(float2*)&out[(size_t)(m0 + rbase + 8) * N_DIM + h * D_DIM + d] = v1;
        }
    }
}

// ---------------------------------------------------------------------------
extern "C" void kernel_launch(void* const* d_in, const int* in_sizes, int n_in,
                              void* d_out, int out_size)
{
    const float* X = (const float*)d_in[0];
    const float* Wq = (const float*)d_in[1];
    const float* Wk = (const float*)d_in[2];
    const float* Wv = (const float*)d_in[3];
    const float* cK = (const float*)d_in[4];
    const float* cV = (const float*)d_in[5];
    float* out = (float*)d_out;

    cudaFuncSetAttribute(qkv_gemm_kernel,
                         cudaFuncAttributeMaxDynamicSharedMemorySize, GEMM_SMEM);
    cudaFuncSetAttribute(attn_kernel,
                         cudaFuncAttributeMaxDynamicSharedMemorySize, AT_SMEM_BYTES);

    dim3 gemm_grid(N_DIM / 128, M_DIM / 128, 3);
    qkv_gemm_kernel<<<gemm_grid, 256, GEMM_SMEM>>>(X, Wq, Wk, Wv);

    dim3 attn_grid(M_DIM / AT_BM, H_DIM);
    attn_kernel<<<attn_grid, 256, AT_SMEM_BYTES>>>(cK, cV, out);
}

// round 4
// speedup vs baseline: 4.3576x; 1.3754x over previous
#include <cuda_runtime.h>
#include <cuda_bf16.h>
#include <math.h>
#include <stdint.h>

#define M_DIM 1024
#define N_DIM 4096
#define D_DIM 128
#define H_DIM 32
#define P_POS 2048
#define L_DIM 4096

// --- arch-specific feature gate (tcgen05 only legal in sm_103a-specific pass)
#if defined(__CUDA_ARCH__)
#if defined(__CUDA_ARCH_FEAT_SM103_ALL)
#define HAS_TC 1
#elif defined(__CUDA_ARCH_SPECIFIC__) && (__CUDA_ARCH_SPECIFIC__ == 1030)
#define HAS_TC 1
#endif
#endif
#ifndef HAS_TC
#define HAS_TC 0
#endif

// Scratch: projected Q/K/V [M, N] fp32 row-major.
__device__ float g_Q[M_DIM * (size_t)N_DIM];
__device__ float g_K[M_DIM * (size_t)N_DIM];
__device__ float g_V[M_DIM * (size_t)N_DIM];
// bf16-split operands (only used when tcgen05 available).
__device__ __nv_bfloat16 g_Xhi[M_DIM * (size_t)N_DIM];
__device__ __nv_bfloat16 g_Xlo[M_DIM * (size_t)N_DIM];
__device__ __nv_bfloat16 g_Whi[3 * (size_t)N_DIM * N_DIM];
__device__ __nv_bfloat16 g_Wlo[3 * (size_t)N_DIM * N_DIM];
__device__ int g_tc_flag;

// ---------------------------------------------------------------------------
// helpers
// ---------------------------------------------------------------------------
__device__ __forceinline__ uint32_t f2tf(float f) {
    uint32_t u;
    asm("cvt.rna.tf32.f32 %0, %1;" : "=r"(u) : "f"(f));
    return u;
}

__device__ __forceinline__ void mma_tf32(float* c, const uint32_t* a, const uint32_t* b) {
    asm volatile(
        "mma.sync.aligned.m16n8k8.row.col.f32.tf32.tf32.f32 "
        "{%0,%1,%2,%3},{%4,%5,%6,%7},{%8,%9},{%0,%1,%2,%3};"
        : "+f"(c[0]), "+f"(c[1]), "+f"(c[2]), "+f"(c[3])
        : "r"(a[0]), "r"(a[1]), "r"(a[2]), "r"(a[3]), "r"(b[0]), "r"(b[1]));
}

__device__ __forceinline__ uint32_t smem_u32(const void* p) {
    return (uint32_t)__cvta_generic_to_shared(p);
}

__device__ __forceinline__ void cp16s(uint32_t s, const void* g) {
    asm volatile("cp.async.cg.shared.global [%0], [%1], 16;" :: "r"(s), "l"(g));
}
#define CP_COMMIT asm volatile("cp.async.commit_group;")
#define CP_WAIT0  asm volatile("cp.async.wait_group 0;")

// split fp32 pair -> packed bf16x2 hi and lo words
__device__ __forceinline__ uint32_t split2(float a, float b, uint32_t& lo) {
    __nv_bfloat16 ah = __float2bfloat16_rn(a);
    __nv_bfloat16 bh = __float2bfloat16_rn(b);
    __nv_bfloat16 al = __float2bfloat16_rn(a - __bfloat162float(ah));
    __nv_bfloat16 bl = __float2bfloat16_rn(b - __bfloat162float(bh));
    lo = (uint32_t)__bfloat16_as_ushort(al) | ((uint32_t)__bfloat16_as_ushort(bl) << 16);
    return (uint32_t)__bfloat16_as_ushort(ah) | ((uint32_t)__bfloat16_as_ushort(bh) << 16);
}

#define SWZ(x) ((x) ^ ((((uint32_t)(x)) >> 3) & 0x70))

// ---------------------------------------------------------------------------
// probe: publish compile-time tcgen05 availability
// ---------------------------------------------------------------------------
__global__ void probe_kernel() {
#if HAS_TC
    g_tc_flag = 1;
#else
    g_tc_flag = 0;
#endif
}

// ---------------------------------------------------------------------------
// Pre-pass 1: X fp32 -> bf16 hi/lo (same layout). No-op unless tcgen05 path.
// ---------------------------------------------------------------------------
__global__ __launch_bounds__(256) void convert_x_kernel(const float* __restrict__ X) {
    if (!g_tc_flag) return;
    size_t i0 = ((size_t)blockIdx.x * 256 + threadIdx.x) * 8;
    float4 f0 = *(const float4*)&X[i0];
    float4 f1 = *(const float4*)&X[i0 + 4];
    uint4 hi, lo;
    hi.x = split2(f0.x, f0.y, lo.x);
    hi.y = split2(f0.z, f0.w, lo.y);
    hi.z = split2(f1.x, f1.y, lo.z);
    hi.w = split2(f1.z, f1.w, lo.w);
    *(uint4*)&g_Xhi[i0] = hi;
    *(uint4*)&g_Xlo[i0] = lo;
}

// ---------------------------------------------------------------------------
// Pre-pass 2: W [k][n] fp32 -> WT [n][k] bf16 hi/lo. No-op unless tcgen05.
// ---------------------------------------------------------------------------
__global__ __launch_bounds__(256) void convert_w_kernel(
    const float* __restrict__ Wq, const float* __restrict__ Wk,
    const float* __restrict__ Wv)
{
    if (!g_tc_flag) return;
    __shared__ float sm[64][65];
    const float* W = (blockIdx.z == 0) ? Wq : (blockIdx.z == 1) ? Wk : Wv;
    const size_t wo = (size_t)blockIdx.z * N_DIM * N_DIM;
    const int k0 = blockIdx.x * 64;
    const int n0 = blockIdx.y * 64;
    const int tid = threadIdx.x;

#pragma unroll
    for (int j = 0; j < 16; j++) {
        int idx = tid + j * 256;
        int kr = idx >> 6, nc = idx & 63;
        sm[kr][nc] = W[(size_t)(k0 + kr) * N_DIM + n0 + nc];
    }
    __syncthreads();
#pragma unroll
    for (int j = 0; j < 8; j++) {
        int idx = tid + j * 256;
        int ni = idx >> 5, kp = idx & 31;
        float a = sm[kp * 2][ni];
        float b = sm[kp * 2 + 1][ni];
        uint32_t lo, hi = split2(a, b, lo);
        size_t o = wo + (size_t)(n0 + ni) * N_DIM + k0 + kp * 2;
        *(uint32_t*)&g_Whi[o] = hi;
        *(uint32_t*)&g_Wlo[o] = lo;
    }
}

// ---------------------------------------------------------------------------
// tcgen05 bf16x3-split GEMM (only when arch-specific pass exists).
// C[128x256 tile] = X @ W. SS mode, K-chunk 64, double-buffered cp.async.
// ---------------------------------------------------------------------------
#define G_ABUF 16384
#define G_BBUF 32768
#define G_BUFSZ (2 * G_ABUF + 2 * G_BBUF)
#define TC_SMEM (2048 + 2 * G_BUFSZ)
#define G_IDESC 0x8400490u   // f32 acc, bf16 a/b, N=256, M=128
#define G_NCH 64

#if HAS_TC
__device__ __forceinline__ uint32_t elect1() {
    uint32_t p;
    asm volatile("{\n\t.reg .pred p;\n\telect.sync _|p, 0xFFFFFFFF;\n\t"
                 "selp.b32 %0, 1, 0, p;\n\t}" : "=r"(p));
    return p;
}
__device__ __forceinline__ void mbar_init(uint32_t m, uint32_t cnt) {
    asm volatile("mbarrier.init.shared.b64 [%0], %1;" :: "r"(m), "r"(cnt) : "memory");
}
__device__ __forceinline__ void mbar_wait(uint32_t m, uint32_t parity) {
    uint32_t done;
    asm volatile(
        "{\n\t.reg .pred p;\n\t"
        "mbarrier.try_wait.parity.acquire.cta.shared::cta.b64 p, [%1], %2;\n\t"
        "selp.b32 %0, 1, 0, p;\n\t}"
        : "=r"(done) : "r"(m), "r"(parity) : "memory");
    if (!done) {
        asm volatile(
            "{\n\t.reg .pred P1;\n\t"
            "WL_%=:\n\t"
            "mbarrier.try_wait.parity.acquire.cta.shared::cta.b64 P1, [%0], %1, 0x989680;\n\t"
            "@P1 bra.uni WD_%=;\n\t"
            "bra.uni WL_%=;\n\t"
            "WD_%=:\n\t}"
            :: "r"(m), "r"(parity) : "memory");
    }
}
__device__ __forceinline__ uint64_t mk_desc(uint32_t addr) {
    const uint64_t base = (uint64_t(2) << 61) | (uint64_t(1) << 46) |
                          (uint64_t(64) << 32) | (uint64_t(1) << 16);
    return base | ((uint64_t)(addr >> 4) & 0x3FFF);
}
__device__ __forceinline__ void mma_bf16_ss(uint32_t d, uint64_t ad, uint64_t bd,
                                            uint32_t idesc, uint32_t en) {
    asm volatile(
        "{\n\t.reg .pred p;\n\t"
        "setp.ne.u32 p, %4, 0;\n\t"
        "tcgen05.mma.cta_group::1.kind::f16 [%0], %1, %2, %3, {%5,%5,%5,%5}, p;\n\t}"
        :: "r"(d), "l"(ad), "l"(bd), "r"(idesc), "r"(en), "r"(0u) : "memory");
}
#endif  // HAS_TC

__global__ __launch_bounds__(256) void qkv_gemm_tc()
{
#if HAS_TC
    extern __shared__ char smem[];
    const uint32_t sb = smem_u32(smem);
    const uint32_t bufbase = (sb + 1024 + 1023) & ~1023u;
    const int tid = threadIdx.x;
    const int lane = tid & 31;
    const int wid = tid >> 5;
    const int row0 = blockIdx.y * 128;
    const int col0 = blockIdx.x * 256;
    const size_t wbase = (size_t)blockIdx.z * N_DIM * N_DIM;
    float* C = (blockIdx.z == 0) ? g_Q : (blockIdx.z == 1) ? g_K : g_V;

    if (wid == 0) {
        asm volatile("tcgen05.alloc.cta_group::1.sync.aligned.shared::cta.b32 [%0], %1;"
                     :: "r"(sb), "r"(256u) : "memory");
    }
    if (tid == 0) {
        mbar_init(sb + 16, 1);
        mbar_init(sb + 24, 1);
    }
    __syncthreads();
    uint32_t tmem;
    asm volatile("ld.shared.b32 %0, [%1];" : "=r"(tmem) : "r"(sb));

    int wcnt[2] = {0, 0};
    for (int it = 0; it < G_NCH; it++) {
        const int b = it & 1;
        const uint32_t bufb = bufbase + b * G_BUFSZ;
        if (it >= 2) {
            mbar_wait(sb + 16 + b * 8, wcnt[b] & 1);
            wcnt[b]++;
        }
        const int k0 = it * 64;
#pragma unroll
        for (int j = 0; j < 4; j++) {
            int u = tid + j * 256;
            int r = u >> 3, c8 = u & 7;
            size_t gsrc = (size_t)(row0 + r) * N_DIM + k0 + c8 * 8;
            uint32_t so = SWZ((uint32_t)(r * 128 + c8 * 16));
            cp16s(bufb + so, &g_Xhi[gsrc]);
            cp16s(bufb + G_ABUF + so, &g_Xlo[gsrc]);
        }
#pragma unroll
        for (int j = 0; j < 8; j++) {
            int u = tid + j * 256;
            int r = u >> 3, c8 = u & 7;
            size_t gsrc = wbase + (size_t)(col0 + r) * N_DIM + k0 + c8 * 8;
            uint32_t so = SWZ((uint32_t)(r * 128 + c8 * 16));
            cp16s(bufb + 2 * G_ABUF + so, &g_Whi[gsrc]);
            cp16s(bufb + 2 * G_ABUF + G_BBUF + so, &g_Wlo[gsrc]);
        }
        CP_COMMIT;
        CP_WAIT0;
        asm volatile("fence.proxy.async.shared::cta;" ::: "memory");
        __syncthreads();

        if (wid == 0 && elect1()) {
            asm volatile("fence.proxy.async.shared::cta;" ::: "memory");
            uint64_t dA[2] = {mk_desc(bufb), mk_desc(bufb + G_ABUF)};
            uint64_t dB[2] = {mk_desc(bufb + 2 * G_ABUF),
                              mk_desc(bufb + 2 * G_ABUF + G_BBUF)};
            const int ca[3] = {0, 0, 1};
            const int cb[3] = {0, 1, 0};
#pragma unroll
            for (int c = 0; c < 3; c++)
#pragma unroll
                for (int k8 = 0; k8 < 4; k8++) {
                    uint32_t en = !(it == 0 && c == 0 && k8 == 0);
                    mma_bf16_ss(tmem, dA[ca[c]] + k8 * 2, dB[cb[c]] + k8 * 2,
                                G_IDESC, en);
                }
            asm volatile(
                "tcgen05.commit.cta_group::1.mbarrier::arrive::one.shared::cluster.b64 [%0];"
                :: "r"(sb + 16 + b * 8) : "memory");
        }
    }
    mbar_wait(sb + 16, wcnt[0] & 1);
    mbar_wait(sb + 24, wcnt[1] & 1);
    asm volatile("tcgen05.fence::after_thread_sync;" ::: "memory");
    __syncthreads();

    // epilogue: LDTM -> smem transpose -> coalesced STG
    const int sp = wid & 3;
    const int ch = wid >> 2;
    float* T = (float*)(smem + (bufbase - sb)) + wid * (32 * 33);
#pragma unroll 1
    for (int cbk = 0; cbk < 4; cbk++) {
        int c0 = ch * 128 + cbk * 32;
        uint32_t r[32];
        asm volatile(
            "tcgen05.ld.sync.aligned.32x32b.x32.b32 "
            "{%0,%1,%2,%3,%4,%5,%6,%7,%8,%9,%10,%11,%12,%13,%14,%15,"
            "%16,%17,%18,%19,%20,%21,%22,%23,%24,%25,%26,%27,%28,%29,%30,%31},[%32];"
            : "=r"(r[0]), "=r"(r[1]), "=r"(r[2]), "=r"(r[3]), "=r"(r[4]), "=r"(r[5]),
              "=r"(r[6]), "=r"(r[7]), "=r"(r[8]), "=r"(r[9]), "=r"(r[10]), "=r"(r[11]),
              "=r"(r[12]), "=r"(r[13]), "=r"(r[14]), "=r"(r[15]), "=r"(r[16]), "=r"(r[17]),
              "=r"(r[18]), "=r"(r[19]), "=r"(r[20]), "=r"(r[21]), "=r"(r[22]), "=r"(r[23]),
              "=r"(r[24]), "=r"(r[25]), "=r"(r[26]), "=r"(r[27]), "=r"(r[28]), "=r"(r[29]),
              "=r"(r[30]), "=r"(r[31])
            : "r"(tmem + c0));
        asm volatile("tcgen05.wait::ld.sync.aligned;" ::: "memory");
#pragma unroll
        for (int j = 0; j < 32; j++) T[lane * 33 + j] = __uint_as_float(r[j]);
        __syncwarp();
#pragma unroll
        for (int rr = 0; rr < 32; rr++) {
            C[(size_t)(row0 + sp * 32 + rr) * N_DIM + col0 + c0 + lane] =
                T[rr * 33 + lane];
        }
        __syncwarp();
    }
    __syncthreads();
    if (wid == 0) {
        asm volatile("tcgen05.dealloc.cta_group::1.sync.aligned.b32 %0, %1;"
                     :: "r"(tmem), "r"(256u));
    }
#endif  // HAS_TC
}

// ---------------------------------------------------------------------------
// Fallback GEMM (verified R2 mma.sync tf32 path). Runs only when !g_tc_flag.
// ---------------------------------------------------------------------------
#define A_LD 36
#define B_LD 136
#define FB_BUF (128 * A_LD + 32 * B_LD)
#define FB_SMEM (2 * FB_BUF * 4)

__global__ __launch_bounds__(256, 2) void qkv_gemm_fb(
    const float* __restrict__ X,
    const float* __restrict__ Wq,
    const float* __restrict__ Wk,
    const float* __restrict__ Wv)
{
    if (g_tc_flag) return;
    extern __shared__ float smf[];
    const float* W = (blockIdx.z == 0) ? Wq : (blockIdx.z == 1) ? Wk : Wv;
    float* C = (blockIdx.z == 0) ? g_Q : (blockIdx.z == 1) ? g_K : g_V;

    const int tid = threadIdx.x;
    const int lane = tid & 31;
    const int wid = tid >> 5;
    const int wm = wid & 1;
    const int wn = wid >> 1;
    const int row0 = blockIdx.y * 128;
    const int col0 = blockIdx.x * 128;

    float acc[4][4][4];
#pragma unroll
    for (int i = 0; i < 4; i++)
#pragma unroll
        for (int j = 0; j < 4; j++)
#pragma unroll
            for (int e = 0; e < 4; e++) acc[i][j][e] = 0.0f;

    {
        float* As = smf;
        float* Bs = smf + 128 * A_LD;
#pragma unroll
        for (int i = 0; i < 4; i++) {
            int idx = tid + i * 256;
            int r = idx >> 3, c4 = idx & 7;
            cp16s(smem_u32(&As[r * A_LD + c4 * 4]), &X[(size_t)(row0 + r) * N_DIM + c4 * 4]);
        }
#pragma unroll
        for (int i = 0; i < 4; i++) {
            int idx = tid + i * 256;
            int r = idx >> 5, c4 = idx & 31;
            cp16s(smem_u32(&Bs[r * B_LD + c4 * 4]), &W[(size_t)r * N_DIM + col0 + c4 * 4]);
        }
        CP_COMMIT;
    }

    int buf = 0;
    for (int kc = 0; kc < N_DIM / 32; kc++) {
        CP_WAIT0;
        __syncthreads();
        if (kc + 1 < N_DIM / 32) {
            int k0 = (kc + 1) * 32;
            float* As = smf + (buf ^ 1) * FB_BUF;
            float* Bs = As + 128 * A_LD;
#pragma unroll
            for (int i = 0; i < 4; i++) {
                int idx = tid + i * 256;
                int r = idx >> 3, c4 = idx & 7;
                cp16s(smem_u32(&As[r * A_LD + c4 * 4]),
                      &X[(size_t)(row0 + r) * N_DIM + k0 + c4 * 4]);
            }
#pragma unroll
            for (int i = 0; i < 4; i++) {
                int idx = tid + i * 256;
                int r = idx >> 5, c4 = idx & 31;
                cp16s(smem_u32(&Bs[r * B_LD + c4 * 4]),
                      &W[(size_t)(k0 + r) * N_DIM + col0 + c4 * 4]);
            }
            CP_COMMIT;
        }

        const float* As = smf + buf * FB_BUF;
        const float* Bs = As + 128 * A_LD;
#pragma unroll
        for (int k8 = 0; k8 < 4; k8++) {
            const int kb = k8 * 8;
            uint32_t af[4][4];
#pragma unroll
            for (int mt = 0; mt < 4; mt++) {
                int r = wm * 64 + mt * 16 + (lane >> 2);
                int c = kb + (lane & 3);
                af[mt][0] = f2tf(As[r * A_LD + c]);
                af[mt][1] = f2tf(As[(r + 8) * A_LD + c]);
                af[mt][2] = f2tf(As[r * A_LD + c + 4]);
                af[mt][3] = f2tf(As[(r + 8) * A_LD + c + 4]);
            }
            uint32_t bf[4][2];
#pragma unroll
            for (int nt = 0; nt < 4; nt++) {
                int cc = wn * 32 + nt * 8 + (lane >> 2);
                int rk = kb + (lane & 3);
                bf[nt][0] = f2tf(Bs[rk * B_LD + cc]);
                bf[nt][1] = f2tf(Bs[(rk + 4) * B_LD + cc]);
            }
#pragma unroll
            for (int mt = 0; mt < 4; mt++)
#pragma unroll
                for (int nt = 0; nt < 4; nt++)
                    mma_tf32(acc[mt][nt], af[mt], bf[nt]);
        }
        buf ^= 1;
    }

#pragma unroll
    for (int mt = 0; mt < 4; mt++) {
#pragma unroll
        for (int nt = 0; nt < 4; nt++) {
            int r = row0 + wm * 64 + mt * 16 + (lane >> 2);
            int c = col0 + wn * 32 + nt * 8 + 2 * (lane & 3);
            float2 v0 = make_float2(acc[mt][nt][0], acc[mt][nt][1]);
            float2 v1 = make_float2(acc[mt][nt][2], acc[mt][nt][3]);
            *(float2*)&C[(size_t)r * N_DIM + c] = v0;
            *(float2*)&C[(size_t)(r + 8) * N_DIM + c] = v1;
        }
    }
}

// ---------------------------------------------------------------------------
// Attention (mma.sync tf32): per CTA = (64 q-rows, 1 head). Chunks of 64 l.
// tf32 conversion once at smem-store; fragment loads are raw LDS.
// ---------------------------------------------------------------------------
#define AT_BM 64
#define AT_BL 64
#define KV_LD 132
#define PS_LD 68
#define AT_SMEM_FLOATS (AT_BM * KV_LD + AT_BL * KV_LD + AT_BM * PS_LD + 64 * 4 + 64)
#define AT_SMEM_BYTES (AT_SMEM_FLOATS * 4)

__global__ __launch_bounds__(256, 2) void attn_kernel(
    const float* __restrict__ cacheK,
    const float* __restrict__ cacheV,
    float* __restrict__ out)
{
    extern __shared__ float sma[];
    float* Qs = sma;
    float* KVs = Qs + AT_BM * KV_LD;
    float* Ps = KVs + AT_BL * KV_LD;
    float* rsum_s = Ps + AT_BM * PS_LD;
    float* rtot = rsum_s + 64 * 4;

    const int tid = threadIdx.x;
    const int lane = tid & 31;
    const int wid = tid >> 5;
    const int wm = wid & 1;
    const int wn = wid >> 1;
    const int m0 = blockIdx.x * AT_BM;
    const int h = blockIdx.y;

#pragma unroll
    for (int i = 0; i < 8; i++) {
        int idx = tid + i * 256;
        int m = idx >> 5;
        int d0 = (idx & 31) * 4;
        float4 q = *(const float4*)&g_Q[(size_t)(m0 + m) * N_DIM + h * D_DIM + d0];
        float4 t = make_float4(__uint_as_float(f2tf(q.x)), __uint_as_float(f2tf(q.y)),
                               __uint_as_float(f2tf(q.z)), __uint_as_float(f2tf(q.w)));
        *(float4*)&Qs[m * KV_LD + d0] = t;
    }

    float accO[2][4][4];
#pragma unroll
    for (int i = 0; i < 2; i++)
#pragma unroll
        for (int j = 0; j < 4; j++)
#pragma unroll
            for (int e = 0; e < 4; e++) accO[i][j][e] = 0.0f;
    float rs[2][2] = {{0.f, 0.f}, {0.f, 0.f}};

    for (int l0 = 0; l0 < L_DIM; l0 += AT_BL) {
        const bool fresh = (l0 >= P_POS) && (l0 < P_POS + M_DIM);
        __syncthreads();

#pragma unroll
        for (int i = 0; i < 8; i++) {
            int idx = tid + i * 256;
            int l = idx >> 5;
            int d0 = (idx & 31) * 4;
            float4 kq = fresh
                ? *(const float4*)&g_K[(size_t)(l0 + l - P_POS) * N_DIM + h * D_DIM + d0]
                : *(const float4*)&cacheK[((size_t)h * L_DIM + l0 + l) * D_DIM + d0];
            float4 t = make_float4(__uint_as_float(f2tf(kq.x)), __uint_as_float(f2tf(kq.y)),
                                   __uint_as_float(f2tf(kq.z)), __uint_as_float(f2tf(kq.w)));
            *(float4*)&KVs[l * KV_LD + d0] = t;
        }
        __syncthreads();

        float accS[2][2][4];
#pragma unroll
        for (int i = 0; i < 2; i++)
#pragma unroll
            for (int j = 0; j < 2; j++)
#pragma unroll
                for (int e = 0; e < 4; e++) accS[i][j][e] = 0.0f;

#pragma unroll
        for (int k8 = 0; k8 < 16; k8++) {
            const int kb = k8 * 8;
            uint32_t af[2][4];
#pragma unroll
            for (int mt = 0; mt < 2; mt++) {
                int r = wm * 32 + mt * 16 + (lane >> 2);
                int c = kb + (lane & 3);
                af[mt][0] = __float_as_uint(Qs[r * KV_LD + c]);
                af[mt][1] = __float_as_uint(Qs[(r + 8) * KV_LD + c]);
                af[mt][2] = __float_as_uint(Qs[r * KV_LD + c + 4]);
                af[mt][3] = __float_as_uint(Qs[(r + 8) * KV_LD + c + 4]);
            }
            uint32_t bf[2][2];
#pragma unroll
            for (int nt = 0; nt < 2; nt++) {
                int ln = wn * 16 + nt * 8 + (lane >> 2);
                int d = kb + (lane & 3);
                bf[nt][0] = __float_as_uint(KVs[ln * KV_LD + d]);
                bf[nt][1] = __float_as_uint(KVs[ln * KV_LD + d + 4]);
            }
#pragma unroll
            for (int mt = 0; mt < 2; mt++)
#pragma unroll
                for (int nt = 0; nt < 2; nt++)
                    mma_tf32(accS[mt][nt], af[mt], bf[nt]);
        }

#pragma unroll
        for (int mt = 0; mt < 2; mt++)
#pragma unroll
            for (int nt = 0; nt < 2; nt++)
#pragma unroll
                for (int e = 0; e < 4; e++) {
                    float ev = __expf(accS[mt][nt][e]);
                    int row = wm * 32 + mt * 16 + (lane >> 2) + (e >> 1) * 8;
                    int col = wn * 16 + nt * 8 + 2 * (lane & 3) + (e & 1);
                    Ps[row * PS_LD + col] = __uint_as_float(f2tf(ev));
                    rs[mt][e >> 1] += ev;
                }
        __syncthreads();

#pragma unroll
        for (int i = 0; i < 8; i++) {
            int idx = tid + i * 256;
            int l = idx >> 5;
            int d0 = (idx & 31) * 4;
            float4 v = fresh
                ? *(const float4*)&g_V[(size_t)(l0 + l - P_POS) * N_DIM + h * D_DIM + d0]
                : *(const float4*)&cacheV[((size_t)h * L_DIM + l0 + l) * D_DIM + d0];
            float4 t = make_float4(__uint_as_float(f2tf(v.x)), __uint_as_float(f2tf(v.y)),
                                   __uint_as_float(f2tf(v.z)), __uint_as_float(f2tf(v.w)));
            *(float4*)&KVs[l * KV_LD + d0] = t;
        }
        __syncthreads();

#pragma unroll
        for (int k8 = 0; k8 < 8; k8++) {
            const int kb = k8 * 8;
            uint32_t af[2][4];
#pragma unroll
            for (int mt = 0; mt < 2; mt++) {
                int r = wm * 32 + mt * 16 + (lane >> 2);
                int c = kb + (lane & 3);
                af[mt][0] = __float_as_uint(Ps[r * PS_LD + c]);
                af[mt][1] = __float_as_uint(Ps[(r + 8) * PS_LD + c]);
                af[mt][2] = __float_as_uint(Ps[r * PS_LD + c + 4]);
                af[mt][3] = __float_as_uint(Ps[(r + 8) * PS_LD + c + 4]);
            }
            uint32_t bf[4][2];
#pragma unroll
            for (int nt = 0; nt < 4; nt++) {
                int d = wn * 32 + nt * 8 + (lane >> 2);
                int l = kb + (lane & 3);
                bf[nt][0] = __float_as_uint(KVs[l * KV_LD + d]);
                bf[nt][1] = __float_as_uint(KVs[(l + 4) * KV_LD + d]);
            }
#pragma unroll
            for (int mt = 0; mt < 2; mt++)
#pragma unroll
                for (int nt = 0; nt < 4; nt++)
                    mma_tf32(accO[mt][nt], af[mt], bf[nt]);
        }
    }

#pragma unroll
    for (int mt = 0; mt < 2; mt++)
#pragma unroll
        for (int hh = 0; hh < 2; hh++) {
            float s = rs[mt][hh];
            s += __shfl_xor_sync(0xffffffffu, s, 1);
            s += __shfl_xor_sync(0xffffffffu, s, 2);
            if ((lane & 3) == 0) {
                int row = wm * 32 + mt * 16 + hh * 8 + (lane >> 2);
                rsum_s[row * 4 + wn] = s;
            }
        }
    __syncthreads();
    if (tid < 64) {
        float s = rsum_s[tid * 4 + 0] + rsum_s[tid * 4 + 1] +
                  rsum_s[tid * 4 + 2] + rsum_s[tid * 4 + 3];
        rtot[tid] = 1.0f / s;
    }
    __syncthreads();

#pragma unroll
    for (int mt = 0; mt < 2; mt++) {
        int rbase = wm * 32 + mt * 16 + (lane >> 2);
        float inv0 = rtot[rbase];
        float inv1 = rtot[rbase + 8];
#pragma unroll
        for (int nt = 0; nt < 4; nt++) {
            int d = wn * 32 + nt * 8 + 2 * (lane & 3);
            float2 v0 = make_float2(accO[mt][nt][0] * inv0, accO[mt][nt][1] * inv0);
            float2 v1 = make_float2(accO[mt][nt][2] * inv1, accO[mt][nt][3] * inv1);
            *(float2*)&out[(size_t)(m0 + rbase) * N_DIM + h * D_DIM + d] = v0;
            *(float2*)&out[(size_t)(m0 + rbase + 8) * N_DIM + h * D_DIM + d] = v1;
        }
    }
}

// ---------------------------------------------------------------------------
extern "C" void kernel_launch(void* const* d_in, const int* in_sizes, int n_in,
                              void* d_out, int out_size)
{
    const float* X = (const float*)d_in[0];
    const float* Wq = (const float*)d_in[1];
    const float* Wk = (const float*)d_in[2];
    const float* Wv = (const float*)d_in[3];
    const float* cK = (const float*)d_in[4];
    const float* cV = (const float*)d_in[5];
    float* out = (float*)d_out;

    cudaFuncSetAttribute(qkv_gemm_tc,
                         cudaFuncAttributeMaxDynamicSharedMemorySize, TC_SMEM);
    cudaFuncSetAttribute(qkv_gemm_fb,
                         cudaFuncAttributeMaxDynamicSharedMemorySize, FB_SMEM);
    cudaFuncSetAttribute(attn_kernel,
                         cudaFuncAttributeMaxDynamicSharedMemorySize, AT_SMEM_BYTES);

    probe_kernel<<<1, 1>>>();
    convert_x_kernel<<<2048, 256>>>(X);
    convert_w_kernel<<<dim3(64, 64, 3), 256>>>(Wq, Wk, Wv);
    qkv_gemm_tc<<<dim3(16, 8, 3), 256, TC_SMEM>>>();
    qkv_gemm_fb<<<dim3(32, 8, 3), 256, FB_SMEM>>>(X, Wq, Wk, Wv);
    attn_kernel<<<dim3(M_DIM / AT_BM, H_DIM), 256, AT_SMEM_BYTES>>>(cK, cV, out);
}

// round 5
// speedup vs baseline: 6.8517x; 1.5723x over previous
#include <cuda_runtime.h>
#include <cuda_bf16.h>
#include <math.h>
#include <stdint.h>

#define M_DIM 1024
#define N_DIM 4096
#define D_DIM 128
#define H_DIM 32
#define P_POS 2048
#define L_DIM 4096

// --- arch-specific feature gate (tcgen05 only legal in sm_103a-specific pass)
#if defined(__CUDA_ARCH__)
#if defined(__CUDA_ARCH_FEAT_SM103_ALL)
#define HAS_TC 1
#elif defined(__CUDA_ARCH_SPECIFIC__) && (__CUDA_ARCH_SPECIFIC__ == 1030)
#define HAS_TC 1
#endif
#endif
#ifndef HAS_TC
#define HAS_TC 0
#endif

// bf16-split operands.
__device__ __nv_bfloat16 g_Xhi[M_DIM * (size_t)N_DIM];
__device__ __nv_bfloat16 g_Xlo[M_DIM * (size_t)N_DIM];
__device__ __nv_bfloat16 g_Whi[3 * (size_t)N_DIM * N_DIM];
__device__ __nv_bfloat16 g_Wlo[3 * (size_t)N_DIM * N_DIM];
// GEMM outputs, bf16 hi/lo, [M][N] row-major (col = h*128+d).
__device__ __nv_bfloat16 g_Qhi[M_DIM * (size_t)N_DIM];
__device__ __nv_bfloat16 g_Qlo[M_DIM * (size_t)N_DIM];
__device__ __nv_bfloat16 g_Khi[M_DIM * (size_t)N_DIM];
__device__ __nv_bfloat16 g_Klo[M_DIM * (size_t)N_DIM];
__device__ __nv_bfloat16 g_Vhi[M_DIM * (size_t)N_DIM];
__device__ __nv_bfloat16 g_Vlo[M_DIM * (size_t)N_DIM];
// Merged cache: K_all [H][L][D], V_all transposed [H][D][L].
__device__ __nv_bfloat16 g_KAhi[(size_t)H_DIM * L_DIM * D_DIM];
__device__ __nv_bfloat16 g_KAlo[(size_t)H_DIM * L_DIM * D_DIM];
__device__ __nv_bfloat16 g_VThi[(size_t)H_DIM * D_DIM * L_DIM];
__device__ __nv_bfloat16 g_VTlo[(size_t)H_DIM * D_DIM * L_DIM];

// ---------------------------------------------------------------------------
// helpers
// ---------------------------------------------------------------------------
__device__ __forceinline__ uint32_t smem_u32(const void* p) {
    return (uint32_t)__cvta_generic_to_shared(p);
}
__device__ __forceinline__ void cp16s(uint32_t s, const void* g) {
    asm volatile("cp.async.cg.shared.global [%0], [%1], 16;" :: "r"(s), "l"(g));
}
#define CP_COMMIT asm volatile("cp.async.commit_group;")

__device__ __forceinline__ uint32_t split2(float a, float b, uint32_t& lo) {
    __nv_bfloat16 ah = __float2bfloat16_rn(a);
    __nv_bfloat16 bh = __float2bfloat16_rn(b);
    __nv_bfloat16 al = __float2bfloat16_rn(a - __bfloat162float(ah));
    __nv_bfloat16 bl = __float2bfloat16_rn(b - __bfloat162float(bh));
    lo = (uint32_t)__bfloat16_as_ushort(al) | ((uint32_t)__bfloat16_as_ushort(bl) << 16);
    return (uint32_t)__bfloat16_as_ushort(ah) | ((uint32_t)__bfloat16_as_ushort(bh) << 16);
}

#define SWZ(x) ((x) ^ ((((uint32_t)(x)) >> 3) & 0x70))

#if HAS_TC
__device__ __forceinline__ uint32_t elect1() {
    uint32_t p;
    asm volatile("{\n\t.reg .pred p;\n\telect.sync _|p, 0xFFFFFFFF;\n\t"
                 "selp.b32 %0, 1, 0, p;\n\t}" : "=r"(p));
    return p;
}
__device__ __forceinline__ void mbar_init(uint32_t m, uint32_t cnt) {
    asm volatile("mbarrier.init.shared.b64 [%0], %1;" :: "r"(m), "r"(cnt) : "memory");
}
__device__ __forceinline__ void mbar_wait(uint32_t m, uint32_t parity) {
    uint32_t done;
    asm volatile(
        "{\n\t.reg .pred p;\n\t"
        "mbarrier.try_wait.parity.acquire.cta.shared::cta.b64 p, [%1], %2;\n\t"
        "selp.b32 %0, 1, 0, p;\n\t}"
        : "=r"(done) : "r"(m), "r"(parity) : "memory");
    if (!done) {
        asm volatile(
            "{\n\t.reg .pred P1;\n\t"
            "WL_%=:\n\t"
            "mbarrier.try_wait.parity.acquire.cta.shared::cta.b64 P1, [%0], %1, 0x989680;\n\t"
            "@P1 bra.uni WD_%=;\n\t"
            "bra.uni WL_%=;\n\t"
            "WD_%=:\n\t}"
            :: "r"(m), "r"(parity) : "memory");
    }
}
__device__ __forceinline__ uint64_t mk_desc(uint32_t addr) {
    const uint64_t base = (uint64_t(2) << 61) | (uint64_t(1) << 46) |
                          (uint64_t(64) << 32) | (uint64_t(1) << 16);
    return base | ((uint64_t)(addr >> 4) & 0x3FFF);
}
__device__ __forceinline__ void mma_ss(uint32_t d, uint64_t ad, uint64_t bd,
                                       uint32_t idesc, uint32_t en) {
    asm volatile(
        "{\n\t.reg .pred p;\n\t"
        "setp.ne.u32 p, %4, 0;\n\t"
        "tcgen05.mma.cta_group::1.kind::f16 [%0], %1, %2, %3, {%5,%5,%5,%5}, p;\n\t}"
        :: "r"(d), "l"(ad), "l"(bd), "r"(idesc), "r"(en), "r"(0u) : "memory");
}
__device__ __forceinline__ void mma_ts(uint32_t d, uint32_t at, uint64_t bd,
                                       uint32_t idesc, uint32_t en) {
    asm volatile(
        "{\n\t.reg .pred p;\n\t"
        "setp.ne.u32 p, %4, 0;\n\t"
        "tcgen05.mma.cta_group::1.kind::f16 [%0], [%1], %2, %3, {%5,%5,%5,%5}, p;\n\t}"
        :: "r"(d), "r"(at), "l"(bd), "r"(idesc), "r"(en), "r"(0u) : "memory");
}
#define LDTM32(r, a)                                                            \
    asm volatile(                                                               \
        "tcgen05.ld.sync.aligned.32x32b.x32.b32 "                               \
        "{%0,%1,%2,%3,%4,%5,%6,%7,%8,%9,%10,%11,%12,%13,%14,%15,"               \
        "%16,%17,%18,%19,%20,%21,%22,%23,%24,%25,%26,%27,%28,%29,%30,%31},[%32];" \
        : "=r"((r)[0]), "=r"((r)[1]), "=r"((r)[2]), "=r"((r)[3]),               \
          "=r"((r)[4]), "=r"((r)[5]), "=r"((r)[6]), "=r"((r)[7]),               \
          "=r"((r)[8]), "=r"((r)[9]), "=r"((r)[10]), "=r"((r)[11]),             \
          "=r"((r)[12]), "=r"((r)[13]), "=r"((r)[14]), "=r"((r)[15]),           \
          "=r"((r)[16]), "=r"((r)[17]), "=r"((r)[18]), "=r"((r)[19]),           \
          "=r"((r)[20]), "=r"((r)[21]), "=r"((r)[22]), "=r"((r)[23]),           \
          "=r"((r)[24]), "=r"((r)[25]), "=r"((r)[26]), "=r"((r)[27]),           \
          "=r"((r)[28]), "=r"((r)[29]), "=r"((r)[30]), "=r"((r)[31])            \
        : "r"(a))
#define STTM32(a, r)                                                            \
    asm volatile(                                                               \
        "tcgen05.st.sync.aligned.32x32b.x32.b32 [%0], "                         \
        "{%1,%2,%3,%4,%5,%6,%7,%8,%9,%10,%11,%12,%13,%14,%15,%16,"              \
        "%17,%18,%19,%20,%21,%22,%23,%24,%25,%26,%27,%28,%29,%30,%31,%32};"     \
        :: "r"(a),                                                              \
           "r"((r)[0]), "r"((r)[1]), "r"((r)[2]), "r"((r)[3]),                  \
           "r"((r)[4]), "r"((r)[5]), "r"((r)[6]), "r"((r)[7]),                  \
           "r"((r)[8]), "r"((r)[9]), "r"((r)[10]), "r"((r)[11]),                \
           "r"((r)[12]), "r"((r)[13]), "r"((r)[14]), "r"((r)[15]),              \
           "r"((r)[16]), "r"((r)[17]), "r"((r)[18]), "r"((r)[19]),              \
           "r"((r)[20]), "r"((r)[21]), "r"((r)[22]), "r"((r)[23]),              \
           "r"((r)[24]), "r"((r)[25]), "r"((r)[26]), "r"((r)[27]),              \
           "r"((r)[28]), "r"((r)[29]), "r"((r)[30]), "r"((r)[31])               \
        : "memory")

// load a 128x128 bf16 tile (atom-blocked K-major SW128, 256B logical rows)
__device__ __forceinline__ void ld_tile(uint32_t sdst, const __nv_bfloat16* g,
                                        size_t stride, int tid) {
#pragma unroll
    for (int j = 0; j < 8; j++) {
        int u = tid + j * 256;
        int r = u >> 4;
        int c8 = u & 15;
        uint32_t so = (uint32_t)(((r >> 3) + (c8 >> 3) * 16) * 1024 +
                                 (r & 7) * 128 + (c8 & 7) * 16);
        cp16s(sdst + SWZ(so), g + (size_t)r * stride + c8 * 8);
    }
}
#endif  // HAS_TC

// ---------------------------------------------------------------------------
// Pre-pass: X fp32 -> bf16 hi/lo
// ---------------------------------------------------------------------------
__global__ __launch_bounds__(256) void convert_x_kernel(const float* __restrict__ X) {
    size_t i0 = ((size_t)blockIdx.x * 256 + threadIdx.x) * 8;
    float4 f0 = *(const float4*)&X[i0];
    float4 f1 = *(const float4*)&X[i0 + 4];
    uint4 hi, lo;
    hi.x = split2(f0.x, f0.y, lo.x);
    hi.y = split2(f0.z, f0.w, lo.y);
    hi.z = split2(f1.x, f1.y, lo.z);
    hi.w = split2(f1.z, f1.w, lo.w);
    *(uint4*)&g_Xhi[i0] = hi;
    *(uint4*)&g_Xlo[i0] = lo;
}

// ---------------------------------------------------------------------------
// Pre-pass: W [k][n] fp32 -> WT [n][k] bf16 hi/lo
// ---------------------------------------------------------------------------
__global__ __launch_bounds__(256) void convert_w_kernel(
    const float* __restrict__ Wq, const float* __restrict__ Wk,
    const float* __restrict__ Wv)
{
    __shared__ float sm[64][65];
    const float* W = (blockIdx.z == 0) ? Wq : (blockIdx.z == 1) ? Wk : Wv;
    const size_t wo = (size_t)blockIdx.z * N_DIM * N_DIM;
    const int k0 = blockIdx.x * 64;
    const int n0 = blockIdx.y * 64;
    const int tid = threadIdx.x;

#pragma unroll
    for (int j = 0; j < 16; j++) {
        int idx = tid + j * 256;
        int kr = idx >> 6, nc = idx & 63;
        sm[kr][nc] = W[(size_t)(k0 + kr) * N_DIM + n0 + nc];
    }
    __syncthreads();
#pragma unroll
    for (int j = 0; j < 8; j++) {
        int idx = tid + j * 256;
        int ni = idx >> 5, kp = idx & 31;
        float a = sm[kp * 2][ni];
        float b = sm[kp * 2 + 1][ni];
        uint32_t lo, hi = split2(a, b, lo);
        size_t o = wo + (size_t)(n0 + ni) * N_DIM + k0 + kp * 2;
        *(uint32_t*)&g_Whi[o] = hi;
        *(uint32_t*)&g_Wlo[o] = lo;
    }
}

// ---------------------------------------------------------------------------
// tcgen05 bf16x3-split GEMM: [M,4096]@[4096,4096], z selects weight.
// Emits bf16 hi/lo outputs directly.
// ---------------------------------------------------------------------------
#define G_ABUF 16384
#define G_BBUF 32768
#define G_BUFSZ (2 * G_ABUF + 2 * G_BBUF)
#define TC_SMEM (2048 + 2 * G_BUFSZ)
#define G_IDESC 0x8400490u
#define G_NCH 64

__global__ __launch_bounds__(256) void qkv_gemm_tc()
{
#if HAS_TC
    extern __shared__ char smem[];
    const uint32_t sb = smem_u32(smem);
    const uint32_t bufbase = (sb + 1024 + 1023) & ~1023u;
    const int tid = threadIdx.x;
    const int lane = tid & 31;
    const int wid = tid >> 5;
    const int row0 = blockIdx.y * 128;
    const int col0 = blockIdx.x * 256;
    const size_t wbase = (size_t)blockIdx.z * N_DIM * N_DIM;
    __nv_bfloat16* Chi = (blockIdx.z == 0) ? g_Qhi : (blockIdx.z == 1) ? g_Khi : g_Vhi;
    __nv_bfloat16* Clo = (blockIdx.z == 0) ? g_Qlo : (blockIdx.z == 1) ? g_Klo : g_Vlo;

    if (wid == 0) {
        asm volatile("tcgen05.alloc.cta_group::1.sync.aligned.shared::cta.b32 [%0], %1;"
                     :: "r"(sb), "r"(256u) : "memory");
    }
    if (tid == 0) {
        mbar_init(sb + 16, 1);
        mbar_init(sb + 24, 1);
    }
    __syncthreads();
    uint32_t tmem;
    asm volatile("ld.shared.b32 %0, [%1];" : "=r"(tmem) : "r"(sb));

    int wcnt[2] = {0, 0};
    for (int it = 0; it < G_NCH; it++) {
        const int b = it & 1;
        const uint32_t bufb = bufbase + b * G_BUFSZ;
        if (it >= 2) {
            mbar_wait(sb + 16 + b * 8, wcnt[b] & 1);
            wcnt[b]++;
        }
        const int k0 = it * 64;
#pragma unroll
        for (int j = 0; j < 4; j++) {
            int u = tid + j * 256;
            int r = u >> 3, c8 = u & 7;
            size_t gsrc = (size_t)(row0 + r) * N_DIM + k0 + c8 * 8;
            uint32_t so = SWZ((uint32_t)(r * 128 + c8 * 16));
            cp16s(bufb + so, &g_Xhi[gsrc]);
            cp16s(bufb + G_ABUF + so, &g_Xlo[gsrc]);
        }
#pragma unroll
        for (int j = 0; j < 8; j++) {
            int u = tid + j * 256;
            int r = u >> 3, c8 = u & 7;
            size_t gsrc = wbase + (size_t)(col0 + r) * N_DIM + k0 + c8 * 8;
            uint32_t so = SWZ((uint32_t)(r * 128 + c8 * 16));
            cp16s(bufb + 2 * G_ABUF + so, &g_Whi[gsrc]);
            cp16s(bufb + 2 * G_ABUF + G_BBUF + so, &g_Wlo[gsrc]);
        }
        CP_COMMIT;
        asm volatile("cp.async.wait_group 0;");
        asm volatile("fence.proxy.async.shared::cta;" ::: "memory");
        __syncthreads();

        if (wid == 0 && elect1()) {
            asm volatile("fence.proxy.async.shared::cta;" ::: "memory");
            uint64_t dA[2] = {mk_desc(bufb), mk_desc(bufb + G_ABUF)};
            uint64_t dB[2] = {mk_desc(bufb + 2 * G_ABUF),
                              mk_desc(bufb + 2 * G_ABUF + G_BBUF)};
            const int ca[3] = {0, 0, 1};
            const int cb[3] = {0, 1, 0};
#pragma unroll
            for (int c = 0; c < 3; c++)
#pragma unroll
                for (int k8 = 0; k8 < 4; k8++) {
                    uint32_t en = !(it == 0 && c == 0 && k8 == 0);
                    mma_ss(tmem, dA[ca[c]] + k8 * 2, dB[cb[c]] + k8 * 2, G_IDESC, en);
                }
            asm volatile(
                "tcgen05.commit.cta_group::1.mbarrier::arrive::one.shared::cluster.b64 [%0];"
                :: "r"(sb + 16 + b * 8) : "memory");
        }
    }
    mbar_wait(sb + 16, wcnt[0] & 1);
    mbar_wait(sb + 24, wcnt[1] & 1);
    asm volatile("tcgen05.fence::after_thread_sync;" ::: "memory");
    __syncthreads();

    // epilogue: LDTM -> smem transpose -> split -> coalesced bf16 STG
    const int sp = wid & 3;
    const int ch = wid >> 2;
    float* T = (float*)(smem + (bufbase - sb)) + wid * (32 * 33);
#pragma unroll 1
    for (int cbk = 0; cbk < 4; cbk++) {
        int c0 = ch * 128 + cbk * 32;
        uint32_t r[32];
        LDTM32(r, tmem + c0);
        asm volatile("tcgen05.wait::ld.sync.aligned;" ::: "memory");
#pragma unroll
        for (int j = 0; j < 32; j++) T[lane * 33 + j] = __uint_as_float(r[j]);
        __syncwarp();
#pragma unroll
        for (int rr = 0; rr < 32; rr++) {
            float v = T[rr * 33 + lane];
            __nv_bfloat16 hi = __float2bfloat16_rn(v);
            __nv_bfloat16 lo = __float2bfloat16_rn(v - __bfloat162float(hi));
            size_t o = (size_t)(row0 + sp * 32 + rr) * N_DIM + col0 + c0 + lane;
            Chi[o] = hi;
            Clo[o] = lo;
        }
        __syncwarp();
    }
    __syncthreads();
    if (wid == 0) {
        asm volatile("tcgen05.dealloc.cta_group::1.sync.aligned.b32 %0, %1;"
                     :: "r"(tmem), "r"(256u));
    }
#endif
}

// ---------------------------------------------------------------------------
// Pre-pass: merged K cache -> g_KA [h][l][d] hi/lo
// ---------------------------------------------------------------------------
__global__ __launch_bounds__(256) void build_k_kernel(const float* __restrict__ cacheK)
{
    size_t idx = ((size_t)blockIdx.x * 256 + threadIdx.x) * 8;
    int h = (int)(idx / ((size_t)L_DIM * D_DIM));
    size_t rem = idx - (size_t)h * L_DIM * D_DIM;
    int l = (int)(rem / D_DIM);
    int d = (int)(rem % D_DIM);
    if (l >= P_POS && l < P_POS + M_DIM) {
        size_t s = (size_t)(l - P_POS) * N_DIM + h * D_DIM + d;
        *(uint4*)&g_KAhi[idx] = *(const uint4*)&g_Khi[s];
        *(uint4*)&g_KAlo[idx] = *(const uint4*)&g_Klo[s];
    } else {
        const float* src = &cacheK[idx];
        float4 f0 = *(const float4*)src;
        float4 f1 = *(const float4*)(src + 4);
        uint4 hi, lo;
        hi.x = split2(f0.x, f0.y, lo.x);
        hi.y = split2(f0.z, f0.w, lo.y);
        hi.z = split2(f1.x, f1.y, lo.z);
        hi.w = split2(f1.z, f1.w, lo.w);
        *(uint4*)&g_KAhi[idx] = hi;
        *(uint4*)&g_KAlo[idx] = lo;
    }
}

// ---------------------------------------------------------------------------
// Pre-pass: merged V cache, transposed -> g_VT [h][d][l] hi/lo
// ---------------------------------------------------------------------------
__global__ __launch_bounds__(256) void build_vt_kernel(const float* __restrict__ cacheV)
{
    __shared__ __nv_bfloat16 Shi[64][65];
    __shared__ __nv_bfloat16 Slo[64][65];
    const int l0 = blockIdx.x * 64;
    const int d0 = blockIdx.y * 64;
    const int h = blockIdx.z;
    const int tid = threadIdx.x;
    const bool fresh = (l0 >= P_POS) && (l0 < P_POS + M_DIM);

#pragma unroll
    for (int j = 0; j < 16; j++) {
        int idx = tid + j * 256;
        int lr = idx >> 6, dc = idx & 63;
        __nv_bfloat16 hi, lo;
        if (fresh) {
            size_t s = (size_t)(l0 + lr - P_POS) * N_DIM + h * D_DIM + d0 + dc;
            hi = g_Vhi[s];
            lo = g_Vlo[s];
        } else {
            float v = cacheV[((size_t)h * L_DIM + l0 + lr) * D_DIM + d0 + dc];
            hi = __float2bfloat16_rn(v);
            lo = __float2bfloat16_rn(v - __bfloat162float(hi));
        }
        Shi[lr][dc] = hi;
        Slo[lr][dc] = lo;
    }
    __syncthreads();
#pragma unroll
    for (int j = 0; j < 16; j++) {
        int idx = tid + j * 256;
        int dr = idx >> 6, lc = idx & 63;
        size_t o = ((size_t)h * D_DIM + d0 + dr) * L_DIM + l0 + lc;
        g_VThi[o] = Shi[lc][dr];
        g_VTlo[o] = Slo[lc][dr];
    }
}

// ---------------------------------------------------------------------------
// tcgen05 attention. CTA = (128 q-rows, 1 head). 32 chunks of 128 l.
// S (SS, 3 chains) -> TMEM; exp+split -> STTM P; PV (TS, 3 chains) -> TMEM O.
// ---------------------------------------------------------------------------
#define AT_TILE 32768
#define AQ_HI 0
#define AQ_LO (1 * AT_TILE)
#define AK_HI (2 * AT_TILE)
#define AK_LO (3 * AT_TILE)
#define AV_HI (4 * AT_TILE)
#define AV_LO (5 * AT_TILE)
#define ATTN_SMEM (2112 + 1024 + 6 * AT_TILE)
#define S_IDESC 0x8200490u
#define TM_S 0
#define TM_O 128
#define TM_PHI 256
#define TM_PLO 320

__global__ __launch_bounds__(256) void attn_tc(float* __restrict__ out)
{
#if HAS_TC
    extern __shared__ char smem[];
    const uint32_t sb = smem_u32(smem);
    const uint32_t db = (sb + 1088 + 1023) & ~1023u;
    float* rsum_s = (float*)(smem + 64);   // [128][2]
    const int tid = threadIdx.x;
    const int lane = tid & 31;
    const int wid = tid >> 5;
    const int sp = wid & 3;
    const int ch = wid >> 2;
    const int m0 = blockIdx.x * 128;
    const int h = blockIdx.y;

    const uint32_t mbS = sb + 16;
    const uint32_t mbP = sb + 24;

    if (wid == 0) {
        asm volatile("tcgen05.alloc.cta_group::1.sync.aligned.shared::cta.b32 [%0], %1;"
                     :: "r"(sb), "r"(512u) : "memory");
    }
    if (tid == 0) {
        mbar_init(mbS, 1);
        mbar_init(mbP, 1);
    }
    __syncthreads();
    uint32_t tmem;
    asm volatile("ld.shared.b32 %0, [%1];" : "=r"(tmem) : "r"(sb));

    const __nv_bfloat16* KAh = &g_KAhi[(size_t)h * L_DIM * D_DIM];
    const __nv_bfloat16* KAl = &g_KAlo[(size_t)h * L_DIM * D_DIM];
    const __nv_bfloat16* VTh = &g_VThi[(size_t)h * D_DIM * L_DIM];
    const __nv_bfloat16* VTl = &g_VTlo[(size_t)h * D_DIM * L_DIM];

    // prologue: Q hi/lo + K chunk 0
    ld_tile(db + AQ_HI, &g_Qhi[(size_t)m0 * N_DIM + h * D_DIM], N_DIM, tid);
    ld_tile(db + AQ_LO, &g_Qlo[(size_t)m0 * N_DIM + h * D_DIM], N_DIM, tid);
    ld_tile(db + AK_HI, &KAh[0], D_DIM, tid);
    ld_tile(db + AK_LO, &KAl[0], D_DIM, tid);
    CP_COMMIT;

    const uint64_t DOFF[8] = {0, 2, 4, 6, 1024, 1026, 1028, 1030};
    float rsum = 0.0f;

    for (int it = 0; it < 32; it++) {
        const int l0 = it * 128;
        // s1: VT buffer free (PV of it-1 done)
        if (it > 0) mbar_wait(mbP, (it - 1) & 1);
        // s2: load VT chunk (overlaps S mma)
        ld_tile(db + AV_HI, &VTh[l0], L_DIM, tid);
        ld_tile(db + AV_LO, &VTl[l0], L_DIM, tid);
        CP_COMMIT;
        // s3: K chunk ready (VT may be in flight)
        asm volatile("cp.async.wait_group 1;");
        asm volatile("fence.proxy.async.shared::cta;" ::: "memory");
        __syncthreads();
        // s4: issue S chains
        if (wid == 0 && elect1()) {
            asm volatile("fence.proxy.async.shared::cta;" ::: "memory");
            uint64_t dQ[2] = {mk_desc(db + AQ_HI), mk_desc(db + AQ_LO)};
            uint64_t dK[2] = {mk_desc(db + AK_HI), mk_desc(db + AK_LO)};
            const int ca[3] = {0, 0, 1};
            const int cb[3] = {0, 1, 0};
#pragma unroll
            for (int c = 0; c < 3; c++)
#pragma unroll
                for (int k8 = 0; k8 < 8; k8++) {
                    uint32_t en = !(c == 0 && k8 == 0);
                    mma_ss(tmem + TM_S, dQ[ca[c]] + DOFF[k8], dK[cb[c]] + DOFF[k8],
                           S_IDESC, en);
                }
            asm volatile(
                "tcgen05.commit.cta_group::1.mbarrier::arrive::one.shared::cluster.b64 [%0];"
                :: "r"(mbS) : "memory");
        }
        // s5: S done
        mbar_wait(mbS, it & 1);
        asm volatile("tcgen05.fence::after_thread_sync;" ::: "memory");
        // s6: prefetch next K (overlaps epilogue + PV)
        if (it < 31) {
            ld_tile(db + AK_HI, &KAh[(size_t)(l0 + 128) * D_DIM], D_DIM, tid);
            ld_tile(db + AK_LO, &KAl[(size_t)(l0 + 128) * D_DIM], D_DIM, tid);
            CP_COMMIT;
        }
        // s7: LDTM S -> exp -> split -> STTM P
        {
            uint32_t s0[32], s1[32];
            LDTM32(s0, tmem + TM_S + ch * 64);
            LDTM32(s1, tmem + TM_S + ch * 64 + 32);
            asm volatile("tcgen05.wait::ld.sync.aligned;" ::: "memory");
            uint32_t ph[32], pl[32];
#pragma unroll
            for (int t = 0; t < 16; t++) {
                float e0 = __expf(__uint_as_float(s0[2 * t]));
                float e1 = __expf(__uint_as_float(s0[2 * t + 1]));
                rsum += e0 + e1;
                ph[t] = split2(e0, e1, pl[t]);
            }
#pragma unroll
            for (int t = 0; t < 16; t++) {
                float e0 = __expf(__uint_as_float(s1[2 * t]));
                float e1 = __expf(__uint_as_float(s1[2 * t + 1]));
                rsum += e0 + e1;
                ph[16 + t] = split2(e0, e1, pl[16 + t]);
            }
            uint32_t wofs = ((uint32_t)sp << 21) + ch * 32;
            STTM32(tmem + TM_PHI + wofs, ph);
            STTM32(tmem + TM_PLO + wofs, pl);
            asm volatile("tcgen05.wait::st.sync.aligned;" ::: "memory");
        }
        asm volatile("tcgen05.fence::before_thread_sync;" ::: "memory");
        // s8: VT ready
        if (it < 31) asm volatile("cp.async.wait_group 1;");
        else         asm volatile("cp.async.wait_group 0;");
        asm volatile("fence.proxy.async.shared::cta;" ::: "memory");
        __syncthreads();
        // s9: issue PV chains (TS)
        if (wid == 0 && elect1()) {
            asm volatile("tcgen05.fence::after_thread_sync;" ::: "memory");
            asm volatile("fence.proxy.async.shared::cta;" ::: "memory");
            uint64_t dV[2] = {mk_desc(db + AV_HI), mk_desc(db + AV_LO)};
            const uint32_t pa[3] = {TM_PHI, TM_PHI, TM_PLO};
            const int pb[3] = {0, 1, 0};
#pragma unroll
            for (int c = 0; c < 3; c++)
#pragma unroll
                for (int k8 = 0; k8 < 8; k8++) {
                    uint32_t en = !(it == 0 && c == 0 && k8 == 0);
                    mma_ts(tmem + TM_O, tmem + pa[c] + k8 * 8, dV[pb[c]] + DOFF[k8],
                           S_IDESC, en);
                }
            asm volatile(
                "tcgen05.commit.cta_group::1.mbarrier::arrive::one.shared::cluster.b64 [%0];"
                :: "r"(mbP) : "memory");
        }
    }
    // final PV done
    mbar_wait(mbP, 31 & 1);
    asm volatile("tcgen05.fence::after_thread_sync;" ::: "memory");

    // row sums
    rsum_s[(sp * 32 + lane) * 2 + ch] = rsum;
    __syncthreads();

    // O epilogue: LDTM, scale, smem transpose, coalesced STG
    {
        uint32_t o0[32], o1[32];
        LDTM32(o0, tmem + TM_O + ch * 64);
        LDTM32(o1, tmem + TM_O + ch * 64 + 32);
        asm volatile("tcgen05.wait::ld.sync.aligned;" ::: "memory");
        int row = sp * 32 + lane;
        float inv = 1.0f / (rsum_s[row * 2 + 0] + rsum_s[row * 2 + 1]);
        float* T = (float*)(smem + (db - sb)) + wid * (32 * 65);
#pragma unroll
        for (int j = 0; j < 32; j++) T[lane * 65 + j] = __uint_as_float(o0[j]) * inv;
#pragma unroll
        for (int j = 0; j < 32; j++) T[lane * 65 + 32 + j] = __uint_as_float(o1[j]) * inv;
        __syncwarp();
#pragma unroll
        for (int r = 0; r < 32; r++) {
            size_t o = (size_t)(m0 + sp * 32 + r) * N_DIM + h * D_DIM + ch * 64;
            out[o + lane] = T[r * 65 + lane];
            out[o + 32 + lane] = T[r * 65 + 32 + lane];
        }
    }
    __syncthreads();
    if (wid == 0) {
        asm volatile("tcgen05.dealloc.cta_group::1.sync.aligned.b32 %0, %1;"
                     :: "r"(tmem), "r"(512u));
    }
#endif
}

// ---------------------------------------------------------------------------
extern "C" void kernel_launch(void* const* d_in, const int* in_sizes, int n_in,
                              void* d_out, int out_size)
{
    const float* X = (const float*)d_in[0];
    const float* Wq = (const float*)d_in[1];
    const float* Wk = (const float*)d_in[2];
    const float* Wv = (const float*)d_in[3];
    const float* cK = (const float*)d_in[4];
    const float* cV = (const float*)d_in[5];
    float* out = (float*)d_out;

    cudaFuncSetAttribute(qkv_gemm_tc,
                         cudaFuncAttributeMaxDynamicSharedMemorySize, TC_SMEM);
    cudaFuncSetAttribute(attn_tc,
                         cudaFuncAttributeMaxDynamicSharedMemorySize, ATTN_SMEM);

    convert_x_kernel<<<2048, 256>>>(X);
    convert_w_kernel<<<dim3(64, 64, 3), 256>>>(Wq, Wk, Wv);
    qkv_gemm_tc<<<dim3(16, 8, 3), 256, TC_SMEM>>>();
    build_k_kernel<<<8192, 256>>>(cK);
    build_vt_kernel<<<dim3(64, 2, 32), 256>>>(cV);
    attn_tc<<<dim3(8, 32), 256, ATTN_SMEM>>>(out);
}

// round 6
// speedup vs baseline: 7.2027x; 1.0512x over previous
#include <cuda_runtime.h>
#include <cuda_bf16.h>
#include <math.h>
#include <stdint.h>

#define M_DIM 1024
#define N_DIM 4096
#define D_DIM 128
#define H_DIM 32
#define P_POS 2048
#define L_DIM 4096

// --- arch-specific feature gate (tcgen05 only legal in sm_103a-specific pass)
#if defined(__CUDA_ARCH__)
#if defined(__CUDA_ARCH_FEAT_SM103_ALL)
#define HAS_TC 1
#elif defined(__CUDA_ARCH_SPECIFIC__) && (__CUDA_ARCH_SPECIFIC__ == 1030)
#define HAS_TC 1
#endif
#endif
#ifndef HAS_TC
#define HAS_TC 0
#endif

// bf16-split operands.
__device__ __nv_bfloat16 g_Xhi[M_DIM * (size_t)N_DIM];
__device__ __nv_bfloat16 g_Xlo[M_DIM * (size_t)N_DIM];
__device__ __nv_bfloat16 g_Whi[3 * (size_t)N_DIM * N_DIM];
__device__ __nv_bfloat16 g_Wlo[3 * (size_t)N_DIM * N_DIM];
// GEMM outputs, bf16 hi/lo, [M][N] row-major (col = h*128+d).
__device__ __nv_bfloat16 g_Qhi[M_DIM * (size_t)N_DIM];
__device__ __nv_bfloat16 g_Qlo[M_DIM * (size_t)N_DIM];
__device__ __nv_bfloat16 g_Khi[M_DIM * (size_t)N_DIM];
__device__ __nv_bfloat16 g_Klo[M_DIM * (size_t)N_DIM];
__device__ __nv_bfloat16 g_Vhi[M_DIM * (size_t)N_DIM];
__device__ __nv_bfloat16 g_Vlo[M_DIM * (size_t)N_DIM];
// Merged cache: K_all [H][L][D], V_all transposed [H][D][L].
__device__ __nv_bfloat16 g_KAhi[(size_t)H_DIM * L_DIM * D_DIM];
__device__ __nv_bfloat16 g_KAlo[(size_t)H_DIM * L_DIM * D_DIM];
__device__ __nv_bfloat16 g_VThi[(size_t)H_DIM * D_DIM * L_DIM];
__device__ __nv_bfloat16 g_VTlo[(size_t)H_DIM * D_DIM * L_DIM];

// ---------------------------------------------------------------------------
// helpers
// ---------------------------------------------------------------------------
__device__ __forceinline__ uint32_t smem_u32(const void* p) {
    return (uint32_t)__cvta_generic_to_shared(p);
}
__device__ __forceinline__ void cp16s(uint32_t s, const void* g) {
    asm volatile("cp.async.cg.shared.global [%0], [%1], 16;" :: "r"(s), "l"(g));
}
#define CP_COMMIT asm volatile("cp.async.commit_group;")

__device__ __forceinline__ uint32_t split2(float a, float b, uint32_t& lo) {
    __nv_bfloat16 ah = __float2bfloat16_rn(a);
    __nv_bfloat16 bh = __float2bfloat16_rn(b);
    __nv_bfloat16 al = __float2bfloat16_rn(a - __bfloat162float(ah));
    __nv_bfloat16 bl = __float2bfloat16_rn(b - __bfloat162float(bh));
    lo = (uint32_t)__bfloat16_as_ushort(al) | ((uint32_t)__bfloat16_as_ushort(bl) << 16);
    return (uint32_t)__bfloat16_as_ushort(ah) | ((uint32_t)__bfloat16_as_ushort(bh) << 16);
}

#define SWZ(x) ((x) ^ ((((uint32_t)(x)) >> 3) & 0x70))

#if HAS_TC
__device__ __forceinline__ uint32_t elect1() {
    uint32_t p;
    asm volatile("{\n\t.reg .pred p;\n\telect.sync _|p, 0xFFFFFFFF;\n\t"
                 "selp.b32 %0, 1, 0, p;\n\t}" : "=r"(p));
    return p;
}
__device__ __forceinline__ void mbar_init(uint32_t m, uint32_t cnt) {
    asm volatile("mbarrier.init.shared.b64 [%0], %1;" :: "r"(m), "r"(cnt) : "memory");
}
__device__ __forceinline__ void mbar_wait(uint32_t m, uint32_t parity) {
    uint32_t done;
    asm volatile(
        "{\n\t.reg .pred p;\n\t"
        "mbarrier.try_wait.parity.acquire.cta.shared::cta.b64 p, [%1], %2;\n\t"
        "selp.b32 %0, 1, 0, p;\n\t}"
        : "=r"(done) : "r"(m), "r"(parity) : "memory");
    if (!done) {
        asm volatile(
            "{\n\t.reg .pred P1;\n\t"
            "WL_%=:\n\t"
            "mbarrier.try_wait.parity.acquire.cta.shared::cta.b64 P1, [%0], %1, 0x989680;\n\t"
            "@P1 bra.uni WD_%=;\n\t"
            "bra.uni WL_%=;\n\t"
            "WD_%=:\n\t}"
            :: "r"(m), "r"(parity) : "memory");
    }
}
__device__ __forceinline__ uint64_t mk_desc(uint32_t addr) {
    const uint64_t base = (uint64_t(2) << 61) | (uint64_t(1) << 46) |
                          (uint64_t(64) << 32) | (uint64_t(1) << 16);
    return base | ((uint64_t)(addr >> 4) & 0x3FFF);
}
__device__ __forceinline__ void mma_ss(uint32_t d, uint64_t ad, uint64_t bd,
                                       uint32_t idesc, uint32_t en) {
    asm volatile(
        "{\n\t.reg .pred p;\n\t"
        "setp.ne.u32 p, %4, 0;\n\t"
        "tcgen05.mma.cta_group::1.kind::f16 [%0], %1, %2, %3, {%5,%5,%5,%5}, p;\n\t}"
        :: "r"(d), "l"(ad), "l"(bd), "r"(idesc), "r"(en), "r"(0u) : "memory");
}
__device__ __forceinline__ void mma_ts(uint32_t d, uint32_t at, uint64_t bd,
                                       uint32_t idesc, uint32_t en) {
    asm volatile(
        "{\n\t.reg .pred p;\n\t"
        "setp.ne.u32 p, %4, 0;\n\t"
        "tcgen05.mma.cta_group::1.kind::f16 [%0], [%1], %2, %3, {%5,%5,%5,%5}, p;\n\t}"
        :: "r"(d), "r"(at), "l"(bd), "r"(idesc), "r"(en), "r"(0u) : "memory");
}
#define LDTM32(r, a)                                                            \
    asm volatile(                                                               \
        "tcgen05.ld.sync.aligned.32x32b.x32.b32 "                               \
        "{%0,%1,%2,%3,%4,%5,%6,%7,%8,%9,%10,%11,%12,%13,%14,%15,"               \
        "%16,%17,%18,%19,%20,%21,%22,%23,%24,%25,%26,%27,%28,%29,%30,%31},[%32];" \
        : "=r"((r)[0]), "=r"((r)[1]), "=r"((r)[2]), "=r"((r)[3]),               \
          "=r"((r)[4]), "=r"((r)[5]), "=r"((r)[6]), "=r"((r)[7]),               \
          "=r"((r)[8]), "=r"((r)[9]), "=r"((r)[10]), "=r"((r)[11]),             \
          "=r"((r)[12]), "=r"((r)[13]), "=r"((r)[14]), "=r"((r)[15]),           \
          "=r"((r)[16]), "=r"((r)[17]), "=r"((r)[18]), "=r"((r)[19]),           \
          "=r"((r)[20]), "=r"((r)[21]), "=r"((r)[22]), "=r"((r)[23]),           \
          "=r"((r)[24]), "=r"((r)[25]), "=r"((r)[26]), "=r"((r)[27]),           \
          "=r"((r)[28]), "=r"((r)[29]), "=r"((r)[30]), "=r"((r)[31])            \
        : "r"(a))
#define STTM32(a, r)                                                            \
    asm volatile(                                                               \
        "tcgen05.st.sync.aligned.32x32b.x32.b32 [%0], "                         \
        "{%1,%2,%3,%4,%5,%6,%7,%8,%9,%10,%11,%12,%13,%14,%15,%16,"              \
        "%17,%18,%19,%20,%21,%22,%23,%24,%25,%26,%27,%28,%29,%30,%31,%32};"     \
        :: "r"(a),                                                              \
           "r"((r)[0]), "r"((r)[1]), "r"((r)[2]), "r"((r)[3]),                  \
           "r"((r)[4]), "r"((r)[5]), "r"((r)[6]), "r"((r)[7]),                  \
           "r"((r)[8]), "r"((r)[9]), "r"((r)[10]), "r"((r)[11]),                \
           "r"((r)[12]), "r"((r)[13]), "r"((r)[14]), "r"((r)[15]),              \
           "r"((r)[16]), "r"((r)[17]), "r"((r)[18]), "r"((r)[19]),              \
           "r"((r)[20]), "r"((r)[21]), "r"((r)[22]), "r"((r)[23]),              \
           "r"((r)[24]), "r"((r)[25]), "r"((r)[26]), "r"((r)[27]),              \
           "r"((r)[28]), "r"((r)[29]), "r"((r)[30]), "r"((r)[31])               \
        : "memory")

// load a 128x128 bf16 tile (atom-blocked K-major SW128, 256B logical rows)
__device__ __forceinline__ void ld_tile(uint32_t sdst, const __nv_bfloat16* g,
                                        size_t stride, int tid) {
#pragma unroll
    for (int j = 0; j < 8; j++) {
        int u = tid + j * 256;
        int r = u >> 4;
        int c8 = u & 15;
        uint32_t so = (uint32_t)(((r >> 3) + (c8 >> 3) * 16) * 1024 +
                                 (r & 7) * 128 + (c8 & 7) * 16);
        cp16s(sdst + SWZ(so), g + (size_t)r * stride + c8 * 8);
    }
}
#endif  // HAS_TC

// ---------------------------------------------------------------------------
// Pre-pass: X fp32 -> bf16 hi/lo
// ---------------------------------------------------------------------------
__global__ __launch_bounds__(256) void convert_x_kernel(const float* __restrict__ X) {
    size_t i0 = ((size_t)blockIdx.x * 256 + threadIdx.x) * 8;
    float4 f0 = *(const float4*)&X[i0];
    float4 f1 = *(const float4*)&X[i0 + 4];
    uint4 hi, lo;
    hi.x = split2(f0.x, f0.y, lo.x);
    hi.y = split2(f0.z, f0.w, lo.y);
    hi.z = split2(f1.x, f1.y, lo.z);
    hi.w = split2(f1.z, f1.w, lo.w);
    *(uint4*)&g_Xhi[i0] = hi;
    *(uint4*)&g_Xlo[i0] = lo;
}

// ---------------------------------------------------------------------------
// Pre-pass: W [k][n] fp32 -> WT [n][k] bf16 hi/lo
// ---------------------------------------------------------------------------
__global__ __launch_bounds__(256) void convert_w_kernel(
    const float* __restrict__ Wq, const float* __restrict__ Wk,
    const float* __restrict__ Wv)
{
    __shared__ float sm[64][65];
    const float* W = (blockIdx.z == 0) ? Wq : (blockIdx.z == 1) ? Wk : Wv;
    const size_t wo = (size_t)blockIdx.z * N_DIM * N_DIM;
    const int k0 = blockIdx.x * 64;
    const int n0 = blockIdx.y * 64;
    const int tid = threadIdx.x;

#pragma unroll
    for (int j = 0; j < 16; j++) {
        int idx = tid + j * 256;
        int kr = idx >> 6, nc = idx & 63;
        sm[kr][nc] = W[(size_t)(k0 + kr) * N_DIM + n0 + nc];
    }
    __syncthreads();
#pragma unroll
    for (int j = 0; j < 8; j++) {
        int idx = tid + j * 256;
        int ni = idx >> 5, kp = idx & 31;
        float a = sm[kp * 2][ni];
        float b = sm[kp * 2 + 1][ni];
        uint32_t lo, hi = split2(a, b, lo);
        size_t o = wo + (size_t)(n0 + ni) * N_DIM + k0 + kp * 2;
        *(uint32_t*)&g_Whi[o] = hi;
        *(uint32_t*)&g_Wlo[o] = lo;
    }
}

// ---------------------------------------------------------------------------
// tcgen05 bf16x3-split GEMM, properly pipelined double buffer.
// ---------------------------------------------------------------------------
#define G_ABUF 16384
#define G_BBUF 32768
#define G_BUFSZ (2 * G_ABUF + 2 * G_BBUF)
#define TC_SMEM (2048 + 2 * G_BUFSZ)
#define G_IDESC 0x8400490u
#define G_NCH 64

#if HAS_TC
__device__ __forceinline__ void gemm_load_chunk(uint32_t bufb, int row0, int col0,
                                                size_t wbase, int k0, int tid) {
#pragma unroll
    for (int j = 0; j < 4; j++) {
        int u = tid + j * 256;
        int r = u >> 3, c8 = u & 7;
        size_t gsrc = (size_t)(row0 + r) * N_DIM + k0 + c8 * 8;
        uint32_t so = SWZ((uint32_t)(r * 128 + c8 * 16));
        cp16s(bufb + so, &g_Xhi[gsrc]);
        cp16s(bufb + G_ABUF + so, &g_Xlo[gsrc]);
    }
#pragma unroll
    for (int j = 0; j < 8; j++) {
        int u = tid + j * 256;
        int r = u >> 3, c8 = u & 7;
        size_t gsrc = wbase + (size_t)(col0 + r) * N_DIM + k0 + c8 * 8;
        uint32_t so = SWZ((uint32_t)(r * 128 + c8 * 16));
        cp16s(bufb + 2 * G_ABUF + so, &g_Whi[gsrc]);
        cp16s(bufb + 2 * G_ABUF + G_BBUF + so, &g_Wlo[gsrc]);
    }
    CP_COMMIT;
}
#endif

__global__ __launch_bounds__(256) void qkv_gemm_tc()
{
#if HAS_TC
    extern __shared__ char smem[];
    const uint32_t sb = smem_u32(smem);
    const uint32_t bufbase = (sb + 1024 + 1023) & ~1023u;
    const int tid = threadIdx.x;
    const int lane = tid & 31;
    const int wid = tid >> 5;
    const int row0 = blockIdx.y * 128;
    const int col0 = blockIdx.x * 256;
    const size_t wbase = (size_t)blockIdx.z * N_DIM * N_DIM;
    __nv_bfloat16* Chi = (blockIdx.z == 0) ? g_Qhi : (blockIdx.z == 1) ? g_Khi : g_Vhi;
    __nv_bfloat16* Clo = (blockIdx.z == 0) ? g_Qlo : (blockIdx.z == 1) ? g_Klo : g_Vlo;

    if (wid == 0) {
        asm volatile("tcgen05.alloc.cta_group::1.sync.aligned.shared::cta.b32 [%0], %1;"
                     :: "r"(sb), "r"(256u) : "memory");
    }
    if (tid == 0) {
        mbar_init(sb + 16, 1);
        mbar_init(sb + 24, 1);
    }
    __syncthreads();
    uint32_t tmem;
    asm volatile("ld.shared.b32 %0, [%1];" : "=r"(tmem) : "r"(sb));

    // prologue: prefetch chunks 0 and 1
    gemm_load_chunk(bufbase, row0, col0, wbase, 0, tid);
    gemm_load_chunk(bufbase + G_BUFSZ, row0, col0, wbase, 64, tid);

    int wcnt[2] = {0, 0};
    for (int it = 0; it < G_NCH; it++) {
        const int b = it & 1;
        const uint32_t bufb = bufbase + b * G_BUFSZ;
        // chunk it loaded (its group older than the in-flight it+1 group)
        asm volatile("cp.async.wait_group 1;");
        asm volatile("fence.proxy.async.shared::cta;" ::: "memory");
        __syncthreads();

        if (wid == 0 && elect1()) {
            asm volatile("fence.proxy.async.shared::cta;" ::: "memory");
            uint64_t dA[2] = {mk_desc(bufb), mk_desc(bufb + G_ABUF)};
            uint64_t dB[2] = {mk_desc(bufb + 2 * G_ABUF),
                              mk_desc(bufb + 2 * G_ABUF + G_BBUF)};
            const int ca[3] = {0, 0, 1};
            const int cb[3] = {0, 1, 0};
#pragma unroll
            for (int c = 0; c < 3; c++)
#pragma unroll
                for (int k8 = 0; k8 < 4; k8++) {
                    uint32_t en = !(it == 0 && c == 0 && k8 == 0);
                    mma_ss(tmem, dA[ca[c]] + k8 * 2, dB[cb[c]] + k8 * 2, G_IDESC, en);
                }
            asm volatile(
                "tcgen05.commit.cta_group::1.mbarrier::arrive::one.shared::cluster.b64 [%0];"
                :: "r"(sb + 16 + b * 8) : "memory");
        }

        if (it + 2 < G_NCH) {
            // wait mma(it) done reading buf b, then prefetch chunk it+2 into it
            mbar_wait(sb + 16 + b * 8, wcnt[b] & 1);
            wcnt[b]++;
            asm volatile("fence.proxy.async.shared::cta;" ::: "memory");
            gemm_load_chunk(bufb, row0, col0, wbase, (it + 2) * 64, tid);
        }
    }
    // drain final commits (32nd per buffer -> parity 31&1)
    mbar_wait(sb + 16, 1);
    mbar_wait(sb + 24, 1);
    asm volatile("tcgen05.fence::after_thread_sync;" ::: "memory");
    __syncthreads();

    // epilogue: LDTM -> smem transpose -> split -> coalesced bf16 STG
    const int sp = wid & 3;
    const int ch = wid >> 2;
    float* T = (float*)(smem + (bufbase - sb)) + wid * (32 * 33);
#pragma unroll 1
    for (int cbk = 0; cbk < 4; cbk++) {
        int c0 = ch * 128 + cbk * 32;
        uint32_t r[32];
        LDTM32(r, tmem + c0);
        asm volatile("tcgen05.wait::ld.sync.aligned;" ::: "memory");
#pragma unroll
        for (int j = 0; j < 32; j++) T[lane * 33 + j] = __uint_as_float(r[j]);
        __syncwarp();
#pragma unroll
        for (int rr = 0; rr < 32; rr++) {
            float v = T[rr * 33 + lane];
            __nv_bfloat16 hi = __float2bfloat16_rn(v);
            __nv_bfloat16 lo = __float2bfloat16_rn(v - __bfloat162float(hi));
            size_t o = (size_t)(row0 + sp * 32 + rr) * N_DIM + col0 + c0 + lane;
            Chi[o] = hi;
            Clo[o] = lo;
        }
        __syncwarp();
    }
    __syncthreads();
    if (wid == 0) {
        asm volatile("tcgen05.dealloc.cta_group::1.sync.aligned.b32 %0, %1;"
                     :: "r"(tmem), "r"(256u));
    }
#endif
}

// ---------------------------------------------------------------------------
// Pre-pass: merged K cache -> g_KA [h][l][d] hi/lo
// ---------------------------------------------------------------------------
__global__ __launch_bounds__(256) void build_k_kernel(const float* __restrict__ cacheK)
{
    size_t idx = ((size_t)blockIdx.x * 256 + threadIdx.x) * 8;
    int h = (int)(idx / ((size_t)L_DIM * D_DIM));
    size_t rem = idx - (size_t)h * L_DIM * D_DIM;
    int l = (int)(rem / D_DIM);
    int d = (int)(rem % D_DIM);
    if (l >= P_POS && l < P_POS + M_DIM) {
        size_t s = (size_t)(l - P_POS) * N_DIM + h * D_DIM + d;
        *(uint4*)&g_KAhi[idx] = *(const uint4*)&g_Khi[s];
        *(uint4*)&g_KAlo[idx] = *(const uint4*)&g_Klo[s];
    } else {
        const float* src = &cacheK[idx];
        float4 f0 = *(const float4*)src;
        float4 f1 = *(const float4*)(src + 4);
        uint4 hi, lo;
        hi.x = split2(f0.x, f0.y, lo.x);
        hi.y = split2(f0.z, f0.w, lo.y);
        hi.z = split2(f1.x, f1.y, lo.z);
        hi.w = split2(f1.z, f1.w, lo.w);
        *(uint4*)&g_KAhi[idx] = hi;
        *(uint4*)&g_KAlo[idx] = lo;
    }
}

// ---------------------------------------------------------------------------
// Pre-pass: merged V cache, transposed -> g_VT [h][d][l] hi/lo
// ---------------------------------------------------------------------------
__global__ __launch_bounds__(256) void build_vt_kernel(const float* __restrict__ cacheV)
{
    __shared__ __nv_bfloat16 Shi[64][65];
    __shared__ __nv_bfloat16 Slo[64][65];
    const int l0 = blockIdx.x * 64;
    const int d0 = blockIdx.y * 64;
    const int h = blockIdx.z;
    const int tid = threadIdx.x;
    const bool fresh = (l0 >= P_POS) && (l0 < P_POS + M_DIM);

#pragma unroll
    for (int j = 0; j < 16; j++) {
        int idx = tid + j * 256;
        int lr = idx >> 6, dc = idx & 63;
        __nv_bfloat16 hi, lo;
        if (fresh) {
            size_t s = (size_t)(l0 + lr - P_POS) * N_DIM + h * D_DIM + d0 + dc;
            hi = g_Vhi[s];
            lo = g_Vlo[s];
        } else {
            float v = cacheV[((size_t)h * L_DIM + l0 + lr) * D_DIM + d0 + dc];
            hi = __float2bfloat16_rn(v);
            lo = __float2bfloat16_rn(v - __bfloat162float(hi));
        }
        Shi[lr][dc] = hi;
        Slo[lr][dc] = lo;
    }
    __syncthreads();
#pragma unroll
    for (int j = 0; j < 16; j++) {
        int idx = tid + j * 256;
        int dr = idx >> 6, lc = idx & 63;
        size_t o = ((size_t)h * D_DIM + d0 + dr) * L_DIM + l0 + lc;
        g_VThi[o] = Shi[lc][dr];
        g_VTlo[o] = Slo[lc][dr];
    }
}

// ---------------------------------------------------------------------------
// tcgen05 attention, software-pipelined.
// TMEM: S0@0, S1@128, O@256, Phi@384, Plo@448 (512 cols).
// ---------------------------------------------------------------------------
#define AT_TILE 32768
#define AQ_HI 0
#define AQ_LO (1 * AT_TILE)
#define AK_HI (2 * AT_TILE)
#define AK_LO (3 * AT_TILE)
#define AV_HI (4 * AT_TILE)
#define AV_LO (5 * AT_TILE)
#define ATTN_SMEM (2112 + 1024 + 6 * AT_TILE)
#define S_IDESC 0x8200490u
#define TM_S 0
#define TM_O 256
#define TM_PHI 384
#define TM_PLO 448

__global__ __launch_bounds__(256) void attn_tc(float* __restrict__ out)
{
#if HAS_TC
    extern __shared__ char smem[];
    const uint32_t sb = smem_u32(smem);
    const uint32_t db = (sb + 1088 + 1023) & ~1023u;
    float* rsum_s = (float*)(smem + 64);   // [128][2]
    const int tid = threadIdx.x;
    const int lane = tid & 31;
    const int wid = tid >> 5;
    const int sp = wid & 3;
    const int ch = wid >> 2;
    const int m0 = blockIdx.x * 128;
    const int h = blockIdx.y;

    const uint32_t mbS = sb + 16;
    const uint32_t mbP = sb + 24;

    if (wid == 0) {
        asm volatile("tcgen05.alloc.cta_group::1.sync.aligned.shared::cta.b32 [%0], %1;"
                     :: "r"(sb), "r"(512u) : "memory");
    }
    if (tid == 0) {
        mbar_init(mbS, 1);
        mbar_init(mbP, 1);
    }
    __syncthreads();
    uint32_t tmem;
    asm volatile("ld.shared.b32 %0, [%1];" : "=r"(tmem) : "r"(sb));

    const __nv_bfloat16* KAh = &g_KAhi[(size_t)h * L_DIM * D_DIM];
    const __nv_bfloat16* KAl = &g_KAlo[(size_t)h * L_DIM * D_DIM];
    const __nv_bfloat16* VTh = &g_VThi[(size_t)h * D_DIM * L_DIM];
    const __nv_bfloat16* VTl = &g_VTlo[(size_t)h * D_DIM * L_DIM];

    const uint64_t DOFF[8] = {0, 2, 4, 6, 1024, 1026, 1028, 1030};
    const int ca3[3] = {0, 0, 1};
    const int cb3[3] = {0, 1, 0};

    // prologue: Q hi/lo + K chunk 0; then issue S(0)
    ld_tile(db + AQ_HI, &g_Qhi[(size_t)m0 * N_DIM + h * D_DIM], N_DIM, tid);
    ld_tile(db + AQ_LO, &g_Qlo[(size_t)m0 * N_DIM + h * D_DIM], N_DIM, tid);
    ld_tile(db + AK_HI, &KAh[0], D_DIM, tid);
    ld_tile(db + AK_LO, &KAl[0], D_DIM, tid);
    CP_COMMIT;
    asm volatile("cp.async.wait_group 0;");
    asm volatile("fence.proxy.async.shared::cta;" ::: "memory");
    __syncthreads();
    if (wid == 0 && elect1()) {
        asm volatile("fence.proxy.async.shared::cta;" ::: "memory");
        uint64_t dQ[2] = {mk_desc(db + AQ_HI), mk_desc(db + AQ_LO)};
        uint64_t dK[2] = {mk_desc(db + AK_HI), mk_desc(db + AK_LO)};
#pragma unroll
        for (int c = 0; c < 3; c++)
#pragma unroll
            for (int k8 = 0; k8 < 8; k8++)
                mma_ss(tmem + TM_S, dQ[ca3[c]] + DOFF[k8], dK[cb3[c]] + DOFF[k8],
                       S_IDESC, !(c == 0 && k8 == 0));
        asm volatile(
            "tcgen05.commit.cta_group::1.mbarrier::arrive::one.shared::cluster.b64 [%0];"
            :: "r"(mbS) : "memory");
    }

    float rsum = 0.0f;

    for (int it = 0; it < 32; it++) {
        const int l0 = it * 128;
        // 1: S(it) done
        mbar_wait(mbS, it & 1);
        asm volatile("tcgen05.fence::after_thread_sync;" ::: "memory");
        // 2: prefetch K(it+1) (K smem free now)
        if (it < 31) {
            ld_tile(db + AK_HI, &KAh[(size_t)(l0 + 128) * D_DIM], D_DIM, tid);
            ld_tile(db + AK_LO, &KAl[(size_t)(l0 + 128) * D_DIM], D_DIM, tid);
            CP_COMMIT;
        }
        // 3: PV(it-1) done -> P TMEM + V smem free
        if (it > 0) {
            mbar_wait(mbP, (it - 1) & 1);
            asm volatile("tcgen05.fence::after_thread_sync;" ::: "memory");
        }
        // 4: prefetch V(it) (overlaps exp compute)
        ld_tile(db + AV_HI, &VTh[l0], L_DIM, tid);
        ld_tile(db + AV_LO, &VTl[l0], L_DIM, tid);
        CP_COMMIT;
        // 5: LDTM S(it) -> exp -> split -> STTM P
        {
            const uint32_t sbuf = tmem + TM_S + (it & 1) * 128;
            uint32_t s0[32], s1[32];
            LDTM32(s0, sbuf + ch * 64);
            LDTM32(s1, sbuf + ch * 64 + 32);
            asm volatile("tcgen05.wait::ld.sync.aligned;" ::: "memory");
            uint32_t ph[32], pl[32];
#pragma unroll
            for (int t = 0; t < 16; t++) {
                float e0 = __expf(__uint_as_float(s0[2 * t]));
                float e1 = __expf(__uint_as_float(s0[2 * t + 1]));
                rsum += e0 + e1;
                ph[t] = split2(e0, e1, pl[t]);
            }
#pragma unroll
            for (int t = 0; t < 16; t++) {
                float e0 = __expf(__uint_as_float(s1[2 * t]));
                float e1 = __expf(__uint_as_float(s1[2 * t + 1]));
                rsum += e0 + e1;
                ph[16 + t] = split2(e0, e1, pl[16 + t]);
            }
            uint32_t wofs = ((uint32_t)sp << 21) + ch * 32;
            STTM32(tmem + TM_PHI + wofs, ph);
            STTM32(tmem + TM_PLO + wofs, pl);
            asm volatile("tcgen05.wait::st.sync.aligned;" ::: "memory");
        }
        asm volatile("tcgen05.fence::before_thread_sync;" ::: "memory");
        // 6: K(it+1) landed (V still allowed in flight); issue S(it+1)
        if (it < 31) {
            asm volatile("cp.async.wait_group 1;");
            asm volatile("fence.proxy.async.shared::cta;" ::: "memory");
            __syncthreads();
            if (wid == 0 && elect1()) {
                asm volatile("fence.proxy.async.shared::cta;" ::: "memory");
                uint64_t dQ[2] = {mk_desc(db + AQ_HI), mk_desc(db + AQ_LO)};
                uint64_t dK[2] = {mk_desc(db + AK_HI), mk_desc(db + AK_LO)};
                const uint32_t sdst = tmem + TM_S + ((it + 1) & 1) * 128;
#pragma unroll
                for (int c = 0; c < 3; c++)
#pragma unroll
                    for (int k8 = 0; k8 < 8; k8++)
                        mma_ss(sdst, dQ[ca3[c]] + DOFF[k8], dK[cb3[c]] + DOFF[k8],
                               S_IDESC, !(c == 0 && k8 == 0));
                asm volatile(
                    "tcgen05.commit.cta_group::1.mbarrier::arrive::one.shared::cluster.b64 [%0];"
                    :: "r"(mbS) : "memory");
            }
        }
        // 7: V(it) landed; issue PV(it)
        asm volatile("cp.async.wait_group 0;");
        asm volatile("fence.proxy.async.shared::cta;" ::: "memory");
        __syncthreads();
        if (wid == 0 && elect1()) {
            asm volatile("tcgen05.fence::after_thread_sync;" ::: "memory");
            asm volatile("fence.proxy.async.shared::cta;" ::: "memory");
            uint64_t dV[2] = {mk_desc(db + AV_HI), mk_desc(db + AV_LO)};
            const uint32_t pa[3] = {TM_PHI, TM_PHI, TM_PLO};
            const int pb[3] = {0, 1, 0};
#pragma unroll
            for (int c = 0; c < 3; c++)
#pragma unroll
                for (int k8 = 0; k8 < 8; k8++)
                    mma_ts(tmem + TM_O, tmem + pa[c] + k8 * 8, dV[pb[c]] + DOFF[k8],
                           S_IDESC, !(it == 0 && c == 0 && k8 == 0));
            asm volatile(
                "tcgen05.commit.cta_group::1.mbarrier::arrive::one.shared::cluster.b64 [%0];"
                :: "r"(mbP) : "memory");
        }
    }
    // final PV done
    mbar_wait(mbP, 31 & 1);
    asm volatile("tcgen05.fence::after_thread_sync;" ::: "memory");

    // row sums
    rsum_s[(sp * 32 + lane) * 2 + ch] = rsum;
    __syncthreads();

    // O epilogue: LDTM, scale, smem transpose, coalesced STG
    {
        uint32_t o0[32], o1[32];
        LDTM32(o0, tmem + TM_O + ch * 64);
        LDTM32(o1, tmem + TM_O + ch * 64 + 32);
        asm volatile("tcgen05.wait::ld.sync.aligned;" ::: "memory");
        int row = sp * 32 + lane;
        float inv = 1.0f / (rsum_s[row * 2 + 0] + rsum_s[row * 2 + 1]);
        float* T = (float*)(smem + (db - sb)) + wid * (32 * 65);
#pragma unroll
        for (int j = 0; j < 32; j++) T[lane * 65 + j] = __uint_as_float(o0[j]) * inv;
#pragma unroll
        for (int j = 0; j < 32; j++) T[lane * 65 + 32 + j] = __uint_as_float(o1[j]) * inv;
        __syncwarp();
#pragma unroll
        for (int r = 0; r < 32; r++) {
            size_t o = (size_t)(m0 + sp * 32 + r) * N_DIM + h * D_DIM + ch * 64;
            out[o + lane] = T[r * 65 + lane];
            out[o + 32 + lane] = T[r * 65 + 32 + lane];
        }
    }
    __syncthreads();
    if (wid == 0) {
        asm volatile("tcgen05.dealloc.cta_group::1.sync.aligned.b32 %0, %1;"
                     :: "r"(tmem), "r"(512u));
    }
#endif
}

// ---------------------------------------------------------------------------
extern "C" void kernel_launch(void* const* d_in, const int* in_sizes, int n_in,
                              void* d_out, int out_size)
{
    const float* X = (const float*)d_in[0];
    const float* Wq = (const float*)d_in[1];
    const float* Wk = (const float*)d_in[2];
    const float* Wv = (const float*)d_in[3];
    const float* cK = (const float*)d_in[4];
    const float* cV = (const float*)d_in[5];
    float* out = (float*)d_out;

    cudaFuncSetAttribute(qkv_gemm_tc,
                         cudaFuncAttributeMaxDynamicSharedMemorySize, TC_SMEM);
    cudaFuncSetAttribute(attn_tc,
                         cudaFuncAttributeMaxDynamicSharedMemorySize, ATTN_SMEM);

    convert_x_kernel<<<2048, 256>>>(X);
    convert_w_kernel<<<dim3(64, 64, 3), 256>>>(Wq, Wk, Wv);
    qkv_gemm_tc<<<dim3(16, 8, 3), 256, TC_SMEM>>>();
    build_k_kernel<<<8192, 256>>>(cK);
    build_vt_kernel<<<dim3(64, 2, 32), 256>>>(cV);
    attn_tc<<<dim3(8, 32), 256, ATTN_SMEM>>>(out);
}

// round 7
// speedup vs baseline: 7.2484x; 1.0064x over previous
#include <cuda_runtime.h>
#include <cuda_bf16.h>
#include <math.h>
#include <stdint.h>

#define M_DIM 1024
#define N_DIM 4096
#define D_DIM 128
#define H_DIM 32
#define P_POS 2048
#define L_DIM 4096

// --- arch-specific feature gate (tcgen05 only legal in sm_103a-specific pass)
#if defined(__CUDA_ARCH__)
#if defined(__CUDA_ARCH_FEAT_SM103_ALL)
#define HAS_TC 1
#elif defined(__CUDA_ARCH_SPECIFIC__) && (__CUDA_ARCH_SPECIFIC__ == 1030)
#define HAS_TC 1
#endif
#endif
#ifndef HAS_TC
#define HAS_TC 0
#endif

// bf16-split operands.
__device__ __nv_bfloat16 g_Xhi[M_DIM * (size_t)N_DIM];
__device__ __nv_bfloat16 g_Xlo[M_DIM * (size_t)N_DIM];
__device__ __nv_bfloat16 g_Whi[3 * (size_t)N_DIM * N_DIM];
__device__ __nv_bfloat16 g_Wlo[3 * (size_t)N_DIM * N_DIM];
// GEMM outputs, bf16 hi/lo, [M][N] row-major (col = h*128+d).
__device__ __nv_bfloat16 g_Qhi[M_DIM * (size_t)N_DIM];
__device__ __nv_bfloat16 g_Qlo[M_DIM * (size_t)N_DIM];
__device__ __nv_bfloat16 g_Khi[M_DIM * (size_t)N_DIM];
__device__ __nv_bfloat16 g_Klo[M_DIM * (size_t)N_DIM];
__device__ __nv_bfloat16 g_Vhi[M_DIM * (size_t)N_DIM];
__device__ __nv_bfloat16 g_Vlo[M_DIM * (size_t)N_DIM];
// Merged cache: K_all [H][L][D], V_all transposed [H][D][L].
__device__ __nv_bfloat16 g_KAhi[(size_t)H_DIM * L_DIM * D_DIM];
__device__ __nv_bfloat16 g_KAlo[(size_t)H_DIM * L_DIM * D_DIM];
__device__ __nv_bfloat16 g_VThi[(size_t)H_DIM * D_DIM * L_DIM];
__device__ __nv_bfloat16 g_VTlo[(size_t)H_DIM * D_DIM * L_DIM];

// ---------------------------------------------------------------------------
// helpers
// ---------------------------------------------------------------------------
__device__ __forceinline__ uint32_t smem_u32(const void* p) {
    return (uint32_t)__cvta_generic_to_shared(p);
}
__device__ __forceinline__ void cp16s(uint32_t s, const void* g) {
    asm volatile("cp.async.cg.shared.global [%0], [%1], 16;" :: "r"(s), "l"(g));
}
#define CP_COMMIT asm volatile("cp.async.commit_group;")

__device__ __forceinline__ uint32_t split2(float a, float b, uint32_t& lo) {
    __nv_bfloat16 ah = __float2bfloat16_rn(a);
    __nv_bfloat16 bh = __float2bfloat16_rn(b);
    __nv_bfloat16 al = __float2bfloat16_rn(a - __bfloat162float(ah));
    __nv_bfloat16 bl = __float2bfloat16_rn(b - __bfloat162float(bh));
    lo = (uint32_t)__bfloat16_as_ushort(al) | ((uint32_t)__bfloat16_as_ushort(bl) << 16);
    return (uint32_t)__bfloat16_as_ushort(ah) | ((uint32_t)__bfloat16_as_ushort(bh) << 16);
}

#define SWZ(x) ((x) ^ ((((uint32_t)(x)) >> 3) & 0x70))

#if HAS_TC
__device__ __forceinline__ uint32_t elect1() {
    uint32_t p;
    asm volatile("{\n\t.reg .pred p;\n\telect.sync _|p, 0xFFFFFFFF;\n\t"
                 "selp.b32 %0, 1, 0, p;\n\t}" : "=r"(p));
    return p;
}
__device__ __forceinline__ void mbar_init(uint32_t m, uint32_t cnt) {
    asm volatile("mbarrier.init.shared.b64 [%0], %1;" :: "r"(m), "r"(cnt) : "memory");
}
__device__ __forceinline__ void mbar_wait(uint32_t m, uint32_t parity) {
    uint32_t done;
    asm volatile(
        "{\n\t.reg .pred p;\n\t"
        "mbarrier.try_wait.parity.acquire.cta.shared::cta.b64 p, [%1], %2;\n\t"
        "selp.b32 %0, 1, 0, p;\n\t}"
        : "=r"(done) : "r"(m), "r"(parity) : "memory");
    if (!done) {
        asm volatile(
            "{\n\t.reg .pred P1;\n\t"
            "WL_%=:\n\t"
            "mbarrier.try_wait.parity.acquire.cta.shared::cta.b64 P1, [%0], %1, 0x989680;\n\t"
            "@P1 bra.uni WD_%=;\n\t"
            "bra.uni WL_%=;\n\t"
            "WD_%=:\n\t}"
            :: "r"(m), "r"(parity) : "memory");
    }
}
__device__ __forceinline__ uint64_t mk_desc(uint32_t addr) {
    const uint64_t base = (uint64_t(2) << 61) | (uint64_t(1) << 46) |
                          (uint64_t(64) << 32) | (uint64_t(1) << 16);
    return base | ((uint64_t)(addr >> 4) & 0x3FFF);
}
__device__ __forceinline__ void mma_ss(uint32_t d, uint64_t ad, uint64_t bd,
                                       uint32_t idesc, uint32_t en) {
    asm volatile(
        "{\n\t.reg .pred p;\n\t"
        "setp.ne.u32 p, %4, 0;\n\t"
        "tcgen05.mma.cta_group::1.kind::f16 [%0], %1, %2, %3, {%5,%5,%5,%5}, p;\n\t}"
        :: "r"(d), "l"(ad), "l"(bd), "r"(idesc), "r"(en), "r"(0u) : "memory");
}
__device__ __forceinline__ void mma_ts(uint32_t d, uint32_t at, uint64_t bd,
                                       uint32_t idesc, uint32_t en) {
    asm volatile(
        "{\n\t.reg .pred p;\n\t"
        "setp.ne.u32 p, %4, 0;\n\t"
        "tcgen05.mma.cta_group::1.kind::f16 [%0], [%1], %2, %3, {%5,%5,%5,%5}, p;\n\t}"
        :: "r"(d), "r"(at), "l"(bd), "r"(idesc), "r"(en), "r"(0u) : "memory");
}
#define LDTM32(r, a)                                                            \
    asm volatile(                                                               \
        "tcgen05.ld.sync.aligned.32x32b.x32.b32 "                               \
        "{%0,%1,%2,%3,%4,%5,%6,%7,%8,%9,%10,%11,%12,%13,%14,%15,"               \
        "%16,%17,%18,%19,%20,%21,%22,%23,%24,%25,%26,%27,%28,%29,%30,%31},[%32];" \
        : "=r"((r)[0]), "=r"((r)[1]), "=r"((r)[2]), "=r"((r)[3]),               \
          "=r"((r)[4]), "=r"((r)[5]), "=r"((r)[6]), "=r"((r)[7]),               \
          "=r"((r)[8]), "=r"((r)[9]), "=r"((r)[10]), "=r"((r)[11]),             \
          "=r"((r)[12]), "=r"((r)[13]), "=r"((r)[14]), "=r"((r)[15]),           \
          "=r"((r)[16]), "=r"((r)[17]), "=r"((r)[18]), "=r"((r)[19]),           \
          "=r"((r)[20]), "=r"((r)[21]), "=r"((r)[22]), "=r"((r)[23]),           \
          "=r"((r)[24]), "=r"((r)[25]), "=r"((r)[26]), "=r"((r)[27]),           \
          "=r"((r)[28]), "=r"((r)[29]), "=r"((r)[30]), "=r"((r)[31])            \
        : "r"(a))
#define STTM16(a, r)                                                            \
    asm volatile(                                                               \
        "tcgen05.st.sync.aligned.32x32b.x16.b32 [%0], "                         \
        "{%1,%2,%3,%4,%5,%6,%7,%8,%9,%10,%11,%12,%13,%14,%15,%16};"             \
        :: "r"(a),                                                              \
           "r"((r)[0]), "r"((r)[1]), "r"((r)[2]), "r"((r)[3]),                  \
           "r"((r)[4]), "r"((r)[5]), "r"((r)[6]), "r"((r)[7]),                  \
           "r"((r)[8]), "r"((r)[9]), "r"((r)[10]), "r"((r)[11]),                \
           "r"((r)[12]), "r"((r)[13]), "r"((r)[14]), "r"((r)[15])               \
        : "memory")

// 128x128 bf16 tile (atom-blocked K-major SW128, 256B logical rows)
__device__ __forceinline__ void ld_tile(uint32_t sdst, const __nv_bfloat16* g,
                                        size_t stride, int tid) {
#pragma unroll
    for (int j = 0; j < 8; j++) {
        int u = tid + j * 256;
        int r = u >> 4;
        int c8 = u & 15;
        uint32_t so = (uint32_t)(((r >> 3) + (c8 >> 3) * 16) * 1024 +
                                 (r & 7) * 128 + (c8 & 7) * 16);
        cp16s(sdst + SWZ(so), g + (size_t)r * stride + c8 * 8);
    }
}
// 64x128 bf16 tile (atom-blocked, 8 atoms per 128B-col-block)
__device__ __forceinline__ void ld_tile_k64(uint32_t sdst, const __nv_bfloat16* g,
                                            size_t stride, int tid) {
#pragma unroll
    for (int j = 0; j < 4; j++) {
        int u = tid + j * 256;
        int r = u >> 4;
        int c8 = u & 15;
        uint32_t so = (uint32_t)(((r >> 3) + (c8 >> 3) * 8) * 1024 +
                                 (r & 7) * 128 + (c8 & 7) * 16);
        cp16s(sdst + SWZ(so), g + (size_t)r * stride + c8 * 8);
    }
}
// 128x64 bf16 tile (128B rows, single atom column)
__device__ __forceinline__ void ld_tile_v64(uint32_t sdst, const __nv_bfloat16* g,
                                            size_t stride, int tid) {
#pragma unroll
    for (int j = 0; j < 4; j++) {
        int u = tid + j * 256;
        int r = u >> 3;
        int c8 = u & 7;
        uint32_t so = (uint32_t)((r >> 3) * 1024 + (r & 7) * 128 + c8 * 16);
        cp16s(sdst + SWZ(so), g + (size_t)r * stride + c8 * 8);
    }
}
#endif  // HAS_TC

// ---------------------------------------------------------------------------
// Pre-pass: X fp32 -> bf16 hi/lo
// ---------------------------------------------------------------------------
__global__ __launch_bounds__(256) void convert_x_kernel(const float* __restrict__ X) {
    size_t i0 = ((size_t)blockIdx.x * 256 + threadIdx.x) * 8;
    float4 f0 = *(const float4*)&X[i0];
    float4 f1 = *(const float4*)&X[i0 + 4];
    uint4 hi, lo;
    hi.x = split2(f0.x, f0.y, lo.x);
    hi.y = split2(f0.z, f0.w, lo.y);
    hi.z = split2(f1.x, f1.y, lo.z);
    hi.w = split2(f1.z, f1.w, lo.w);
    *(uint4*)&g_Xhi[i0] = hi;
    *(uint4*)&g_Xlo[i0] = lo;
}

// ---------------------------------------------------------------------------
// Pre-pass: W [k][n] fp32 -> WT [n][k] bf16 hi/lo
// ---------------------------------------------------------------------------
__global__ __launch_bounds__(256) void convert_w_kernel(
    const float* __restrict__ Wq, const float* __restrict__ Wk,
    const float* __restrict__ Wv)
{
    __shared__ float sm[64][65];
    const float* W = (blockIdx.z == 0) ? Wq : (blockIdx.z == 1) ? Wk : Wv;
    const size_t wo = (size_t)blockIdx.z * N_DIM * N_DIM;
    const int k0 = blockIdx.x * 64;
    const int n0 = blockIdx.y * 64;
    const int tid = threadIdx.x;

#pragma unroll
    for (int j = 0; j < 16; j++) {
        int idx = tid + j * 256;
        int kr = idx >> 6, nc = idx & 63;
        sm[kr][nc] = W[(size_t)(k0 + kr) * N_DIM + n0 + nc];
    }
    __syncthreads();
#pragma unroll
    for (int j = 0; j < 8; j++) {
        int idx = tid + j * 256;
        int ni = idx >> 5, kp = idx & 31;
        float a = sm[kp * 2][ni];
        float b = sm[kp * 2 + 1][ni];
        uint32_t lo, hi = split2(a, b, lo);
        size_t o = wo + (size_t)(n0 + ni) * N_DIM + k0 + kp * 2;
        *(uint32_t*)&g_Whi[o] = hi;
        *(uint32_t*)&g_Wlo[o] = lo;
    }
}

// ---------------------------------------------------------------------------
// tcgen05 bf16x3-split GEMM, pipelined double buffer (unchanged from R6).
// ---------------------------------------------------------------------------
#define G_ABUF 16384
#define G_BBUF 32768
#define G_BUFSZ (2 * G_ABUF + 2 * G_BBUF)
#define TC_SMEM (2048 + 2 * G_BUFSZ)
#define G_IDESC 0x8400490u
#define G_NCH 64

#if HAS_TC
__device__ __forceinline__ void gemm_load_chunk(uint32_t bufb, int row0, int col0,
                                                size_t wbase, int k0, int tid) {
#pragma unroll
    for (int j = 0; j < 4; j++) {
        int u = tid + j * 256;
        int r = u >> 3, c8 = u & 7;
        size_t gsrc = (size_t)(row0 + r) * N_DIM + k0 + c8 * 8;
        uint32_t so = SWZ((uint32_t)(r * 128 + c8 * 16));
        cp16s(bufb + so, &g_Xhi[gsrc]);
        cp16s(bufb + G_ABUF + so, &g_Xlo[gsrc]);
    }
#pragma unroll
    for (int j = 0; j < 8; j++) {
        int u = tid + j * 256;
        int r = u >> 3, c8 = u & 7;
        size_t gsrc = wbase + (size_t)(col0 + r) * N_DIM + k0 + c8 * 8;
        uint32_t so = SWZ((uint32_t)(r * 128 + c8 * 16));
        cp16s(bufb + 2 * G_ABUF + so, &g_Whi[gsrc]);
        cp16s(bufb + 2 * G_ABUF + G_BBUF + so, &g_Wlo[gsrc]);
    }
    CP_COMMIT;
}
#endif

__global__ __launch_bounds__(256) void qkv_gemm_tc()
{
#if HAS_TC
    extern __shared__ char smem[];
    const uint32_t sb = smem_u32(smem);
    const uint32_t bufbase = (sb + 1024 + 1023) & ~1023u;
    const int tid = threadIdx.x;
    const int lane = tid & 31;
    const int wid = tid >> 5;
    const int row0 = blockIdx.y * 128;
    const int col0 = blockIdx.x * 256;
    const size_t wbase = (size_t)blockIdx.z * N_DIM * N_DIM;
    __nv_bfloat16* Chi = (blockIdx.z == 0) ? g_Qhi : (blockIdx.z == 1) ? g_Khi : g_Vhi;
    __nv_bfloat16* Clo = (blockIdx.z == 0) ? g_Qlo : (blockIdx.z == 1) ? g_Klo : g_Vlo;

    if (wid == 0) {
        asm volatile("tcgen05.alloc.cta_group::1.sync.aligned.shared::cta.b32 [%0], %1;"
                     :: "r"(sb), "r"(256u) : "memory");
    }
    if (tid == 0) {
        mbar_init(sb + 16, 1);
        mbar_init(sb + 24, 1);
    }
    __syncthreads();
    uint32_t tmem;
    asm volatile("ld.shared.b32 %0, [%1];" : "=r"(tmem) : "r"(sb));

    gemm_load_chunk(bufbase, row0, col0, wbase, 0, tid);
    gemm_load_chunk(bufbase + G_BUFSZ, row0, col0, wbase, 64, tid);

    int wcnt[2] = {0, 0};
    for (int it = 0; it < G_NCH; it++) {
        const int b = it & 1;
        const uint32_t bufb = bufbase + b * G_BUFSZ;
        asm volatile("cp.async.wait_group 1;");
        asm volatile("fence.proxy.async.shared::cta;" ::: "memory");
        __syncthreads();

        if (wid == 0 && elect1()) {
            asm volatile("fence.proxy.async.shared::cta;" ::: "memory");
            uint64_t dA[2] = {mk_desc(bufb), mk_desc(bufb + G_ABUF)};
            uint64_t dB[2] = {mk_desc(bufb + 2 * G_ABUF),
                              mk_desc(bufb + 2 * G_ABUF + G_BBUF)};
            const int ca[3] = {0, 0, 1};
            const int cb[3] = {0, 1, 0};
#pragma unroll
            for (int c = 0; c < 3; c++)
#pragma unroll
                for (int k8 = 0; k8 < 4; k8++) {
                    uint32_t en = !(it == 0 && c == 0 && k8 == 0);
                    mma_ss(tmem, dA[ca[c]] + k8 * 2, dB[cb[c]] + k8 * 2, G_IDESC, en);
                }
            asm volatile(
                "tcgen05.commit.cta_group::1.mbarrier::arrive::one.shared::cluster.b64 [%0];"
                :: "r"(sb + 16 + b * 8) : "memory");
        }

        if (it + 2 < G_NCH) {
            mbar_wait(sb + 16 + b * 8, wcnt[b] & 1);
            wcnt[b]++;
            asm volatile("fence.proxy.async.shared::cta;" ::: "memory");
            gemm_load_chunk(bufb, row0, col0, wbase, (it + 2) * 64, tid);
        }
    }
    mbar_wait(sb + 16, 1);
    mbar_wait(sb + 24, 1);
    asm volatile("tcgen05.fence::after_thread_sync;" ::: "memory");
    __syncthreads();

    const int sp = wid & 3;
    const int ch = wid >> 2;
    float* T = (float*)(smem + (bufbase - sb)) + wid * (32 * 33);
#pragma unroll 1
    for (int cbk = 0; cbk < 4; cbk++) {
        int c0 = ch * 128 + cbk * 32;
        uint32_t r[32];
        LDTM32(r, tmem + c0);
        asm volatile("tcgen05.wait::ld.sync.aligned;" ::: "memory");
#pragma unroll
        for (int j = 0; j < 32; j++) T[lane * 33 + j] = __uint_as_float(r[j]);
        __syncwarp();
#pragma unroll
        for (int rr = 0; rr < 32; rr++) {
            float v = T[rr * 33 + lane];
            __nv_bfloat16 hi = __float2bfloat16_rn(v);
            __nv_bfloat16 lo = __float2bfloat16_rn(v - __bfloat162float(hi));
            size_t o = (size_t)(row0 + sp * 32 + rr) * N_DIM + col0 + c0 + lane;
            Chi[o] = hi;
            Clo[o] = lo;
        }
        __syncwarp();
    }
    __syncthreads();
    if (wid == 0) {
        asm volatile("tcgen05.dealloc.cta_group::1.sync.aligned.b32 %0, %1;"
                     :: "r"(tmem), "r"(256u));
    }
#endif
}

// ---------------------------------------------------------------------------
// Pre-pass: merged K cache -> g_KA [h][l][d] hi/lo
// ---------------------------------------------------------------------------
__global__ __launch_bounds__(256) void build_k_kernel(const float* __restrict__ cacheK)
{
    size_t idx = ((size_t)blockIdx.x * 256 + threadIdx.x) * 8;
    int h = (int)(idx / ((size_t)L_DIM * D_DIM));
    size_t rem = idx - (size_t)h * L_DIM * D_DIM;
    int l = (int)(rem / D_DIM);
    int d = (int)(rem % D_DIM);
    if (l >= P_POS && l < P_POS + M_DIM) {
        size_t s = (size_t)(l - P_POS) * N_DIM + h * D_DIM + d;
        *(uint4*)&g_KAhi[idx] = *(const uint4*)&g_Khi[s];
        *(uint4*)&g_KAlo[idx] = *(const uint4*)&g_Klo[s];
    } else {
        const float* src = &cacheK[idx];
        float4 f0 = *(const float4*)src;
        float4 f1 = *(const float4*)(src + 4);
        uint4 hi, lo;
        hi.x = split2(f0.x, f0.y, lo.x);
        hi.y = split2(f0.z, f0.w, lo.y);
        hi.z = split2(f1.x, f1.y, lo.z);
        hi.w = split2(f1.z, f1.w, lo.w);
        *(uint4*)&g_KAhi[idx] = hi;
        *(uint4*)&g_KAlo[idx] = lo;
    }
}

// ---------------------------------------------------------------------------
// Pre-pass: merged V cache, transposed -> g_VT [h][d][l] hi/lo
// ---------------------------------------------------------------------------
__global__ __launch_bounds__(256) void build_vt_kernel(const float* __restrict__ cacheV)
{
    __shared__ __nv_bfloat16 Shi[64][65];
    __shared__ __nv_bfloat16 Slo[64][65];
    const int l0 = blockIdx.x * 64;
    const int d0 = blockIdx.y * 64;
    const int h = blockIdx.z;
    const int tid = threadIdx.x;
    const bool fresh = (l0 >= P_POS) && (l0 < P_POS + M_DIM);

#pragma unroll
    for (int j = 0; j < 16; j++) {
        int idx = tid + j * 256;
        int lr = idx >> 6, dc = idx & 63;
        __nv_bfloat16 hi, lo;
        if (fresh) {
            size_t s = (size_t)(l0 + lr - P_POS) * N_DIM + h * D_DIM + d0 + dc;
            hi = g_Vhi[s];
            lo = g_Vlo[s];
        } else {
            float v = cacheV[((size_t)h * L_DIM + l0 + lr) * D_DIM + d0 + dc];
            hi = __float2bfloat16_rn(v);
            lo = __float2bfloat16_rn(v - __bfloat162float(hi));
        }
        Shi[lr][dc] = hi;
        Slo[lr][dc] = lo;
    }
    __syncthreads();
#pragma unroll
    for (int j = 0; j < 16; j++) {
        int idx = tid + j * 256;
        int dr = idx >> 6, lc = idx & 63;
        size_t o = ((size_t)h * D_DIM + d0 + dr) * L_DIM + l0 + lc;
        g_VThi[o] = Shi[lc][dr];
        g_VTlo[o] = Slo[lc][dr];
    }
}

// ---------------------------------------------------------------------------
// tcgen05 attention, BL=64, K/V/S double-buffered, early S issue.
// TMEM: S0@0, S1@64, O@128, Phi@256, Plo@288.
// ---------------------------------------------------------------------------
#define A_NCH 64
#define AQ_HI 0
#define AQ_LO 32768
#define AK_BASE 65536           // + buf*32768 + hl*16384
#define AV_BASE 131072          // + buf*32768 + hl*16384
#define ATTN_SMEM (2112 + 1024 + 196608)
#define S_IDESC 0x8100490u      // N=64, M=128
#define PV_IDESC 0x8200490u     // N=128, M=128
#define TM_S 0
#define TM_O 128
#define TM_PHI 256
#define TM_PLO 288

__global__ __launch_bounds__(256) void attn_tc(float* __restrict__ out)
{
#if HAS_TC
    extern __shared__ char smem[];
    const uint32_t sb = smem_u32(smem);
    const uint32_t db = (sb + 1088 + 1023) & ~1023u;
    float* rsum_s = (float*)(smem + 64);   // [128][2]
    const int tid = threadIdx.x;
    const int lane = tid & 31;
    const int wid = tid >> 5;
    const int sp = wid & 3;
    const int ch = wid >> 2;
    const int m0 = blockIdx.x * 128;
    const int h = blockIdx.y;

    const uint32_t mbS = sb + 16;
    const uint32_t mbP = sb + 24;

    if (wid == 0) {
        asm volatile("tcgen05.alloc.cta_group::1.sync.aligned.shared::cta.b32 [%0], %1;"
                     :: "r"(sb), "r"(512u) : "memory");
    }
    if (tid == 0) {
        mbar_init(mbS, 1);
        mbar_init(mbP, 1);
    }
    __syncthreads();
    uint32_t tmem;
    asm volatile("ld.shared.b32 %0, [%1];" : "=r"(tmem) : "r"(sb));

    const __nv_bfloat16* KAh = &g_KAhi[(size_t)h * L_DIM * D_DIM];
    const __nv_bfloat16* KAl = &g_KAlo[(size_t)h * L_DIM * D_DIM];
    const __nv_bfloat16* VTh = &g_VThi[(size_t)h * D_DIM * L_DIM];
    const __nv_bfloat16* VTl = &g_VTlo[(size_t)h * D_DIM * L_DIM];

    const uint64_t DOFF_Q[8] = {0, 2, 4, 6, 1024, 1026, 1028, 1030};
    const uint64_t DOFF_K[8] = {0, 2, 4, 6, 512, 514, 516, 518};
    const int ca3[3] = {0, 0, 1};
    const int cb3[3] = {0, 1, 0};

    // prologue: Q + K0 (group), K1 (group), V0 (group)
    ld_tile(db + AQ_HI, &g_Qhi[(size_t)m0 * N_DIM + h * D_DIM], N_DIM, tid);
    ld_tile(db + AQ_LO, &g_Qlo[(size_t)m0 * N_DIM + h * D_DIM], N_DIM, tid);
    ld_tile_k64(db + AK_BASE, &KAh[0], D_DIM, tid);
    ld_tile_k64(db + AK_BASE + 16384, &KAl[0], D_DIM, tid);
    CP_COMMIT;
    ld_tile_k64(db + AK_BASE + 32768, &KAh[(size_t)64 * D_DIM], D_DIM, tid);
    ld_tile_k64(db + AK_BASE + 49152, &KAl[(size_t)64 * D_DIM], D_DIM, tid);
    CP_COMMIT;
    ld_tile_v64(db + AV_BASE, &VTh[0], L_DIM, tid);
    ld_tile_v64(db + AV_BASE + 16384, &VTl[0], L_DIM, tid);
    CP_COMMIT;

    const uint64_t dQ0 = mk_desc(db + AQ_HI);
    const uint64_t dQ1 = mk_desc(db + AQ_LO);

    // wait Q+K0, issue S(0)
    asm volatile("cp.async.wait_group 2;");
    asm volatile("fence.proxy.async.shared::cta;" ::: "memory");
    __syncthreads();
    if (wid == 0 && elect1()) {
        asm volatile("fence.proxy.async.shared::cta;" ::: "memory");
        uint64_t dQ[2] = {dQ0, dQ1};
        uint64_t dK[2] = {mk_desc(db + AK_BASE), mk_desc(db + AK_BASE + 16384)};
#pragma unroll
        for (int c = 0; c < 3; c++)
#pragma unroll
            for (int k8 = 0; k8 < 8; k8++)
                mma_ss(tmem + TM_S, dQ[ca3[c]] + DOFF_Q[k8], dK[cb3[c]] + DOFF_K[k8],
                       S_IDESC, !(c == 0 && k8 == 0));
        asm volatile(
            "tcgen05.commit.cta_group::1.mbarrier::arrive::one.shared::cluster.b64 [%0];"
            :: "r"(mbS) : "memory");
    }

    float rsum = 0.0f;

    for (int it = 0; it < A_NCH; it++) {
        // 1: S(it) done (K buf it&1 free, S tmem buf it&1 ready)
        mbar_wait(mbS, it & 1);
        asm volatile("tcgen05.fence::after_thread_sync;" ::: "memory");

        // 2+3: K(it+1) landed -> issue S(it+1) immediately (overlaps epilogue)
        if (it < A_NCH - 1) {
            asm volatile("cp.async.wait_group 1;");
            asm volatile("fence.proxy.async.shared::cta;" ::: "memory");
            __syncthreads();
            if (wid == 0 && elect1()) {
                asm volatile("fence.proxy.async.shared::cta;" ::: "memory");
                const uint32_t kb = db + AK_BASE + ((it + 1) & 1) * 32768;
                uint64_t dQ[2] = {dQ0, dQ1};
                uint64_t dK[2] = {mk_desc(kb), mk_desc(kb + 16384)};
                const uint32_t sdst = tmem + TM_S + ((it + 1) & 1) * 64;
#pragma unroll
                for (int c = 0; c < 3; c++)
#pragma unroll
                    for (int k8 = 0; k8 < 8; k8++)
                        mma_ss(sdst, dQ[ca3[c]] + DOFF_Q[k8], dK[cb3[c]] + DOFF_K[k8],
                               S_IDESC, !(c == 0 && k8 == 0));
                asm volatile(
                    "tcgen05.commit.cta_group::1.mbarrier::arrive::one.shared::cluster.b64 [%0];"
                    :: "r"(mbS) : "memory");
            }
        }
        // 4: prefetch K(it+2) into K buf (it&1)
        if (it + 2 < A_NCH) {
            const uint32_t kb = db + AK_BASE + (it & 1) * 32768;
            ld_tile_k64(kb, &KAh[(size_t)(it + 2) * 64 * D_DIM], D_DIM, tid);
            ld_tile_k64(kb + 16384, &KAl[(size_t)(it + 2) * 64 * D_DIM], D_DIM, tid);
            CP_COMMIT;
        }
        // 5: PV(it-1) done (V buf (it-1)&1 free, P consumable)
        if (it > 0) {
            mbar_wait(mbP, (it - 1) & 1);
            asm volatile("tcgen05.fence::after_thread_sync;" ::: "memory");
        }
        // 6: prefetch V(it+1) into V buf ((it+1)&1)
        if (it + 1 < A_NCH) {
            const uint32_t vb = db + AV_BASE + ((it + 1) & 1) * 32768;
            ld_tile_v64(vb, &VTh[(size_t)(it + 1) * 64], L_DIM, tid);
            ld_tile_v64(vb + 16384, &VTl[(size_t)(it + 1) * 64], L_DIM, tid);
            CP_COMMIT;
        }
        // 7: epilogue: LDTM S(it) -> exp -> split -> STTM P
        {
            const uint32_t sbuf = tmem + TM_S + (it & 1) * 64;
            uint32_t s0[32];
            LDTM32(s0, sbuf + ch * 32);
            asm volatile("tcgen05.wait::ld.sync.aligned;" ::: "memory");
            uint32_t ph[16], pl[16];
#pragma unroll
            for (int t = 0; t < 16; t++) {
                float e0 = __expf(__uint_as_float(s0[2 * t]));
                float e1 = __expf(__uint_as_float(s0[2 * t + 1]));
                rsum += e0 + e1;
                ph[t] = split2(e0, e1, pl[t]);
            }
            uint32_t wofs = ((uint32_t)sp << 21) + ch * 16;
            STTM16(tmem + TM_PHI + wofs, ph);
            STTM16(tmem + TM_PLO + wofs, pl);
            asm volatile("tcgen05.wait::st.sync.aligned;" ::: "memory");
        }
        asm volatile("tcgen05.fence::before_thread_sync;" ::: "memory");
        // 8: V(it) landed
        if (it + 2 < A_NCH)      asm volatile("cp.async.wait_group 2;");
        else if (it + 1 < A_NCH) asm volatile("cp.async.wait_group 1;");
        else                     asm volatile("cp.async.wait_group 0;");
        asm volatile("fence.proxy.async.shared::cta;" ::: "memory");
        __syncthreads();
        // 9: issue PV(it)
        if (wid == 0 && elect1()) {
            asm volatile("tcgen05.fence::after_thread_sync;" ::: "memory");
            asm volatile("fence.proxy.async.shared::cta;" ::: "memory");
            const uint32_t vb = db + AV_BASE + (it & 1) * 32768;
            uint64_t dV[2] = {mk_desc(vb), mk_desc(vb + 16384)};
            const uint32_t pa[3] = {TM_PHI, TM_PHI, TM_PLO};
            const int pb[3] = {0, 1, 0};
#pragma unroll
            for (int c = 0; c < 3; c++)
#pragma unroll
                for (int k8 = 0; k8 < 4; k8++)
                    mma_ts(tmem + TM_O, tmem + pa[c] + k8 * 8, dV[pb[c]] + k8 * 2,
                           PV_IDESC, !(it == 0 && c == 0 && k8 == 0));
            asm volatile(
                "tcgen05.commit.cta_group::1.mbarrier::arrive::one.shared::cluster.b64 [%0];"
                :: "r"(mbP) : "memory");
        }
    }
    // final PV done
    mbar_wait(mbP, (A_NCH - 1) & 1);
    asm volatile("tcgen05.fence::after_thread_sync;" ::: "memory");

    // row sums
    rsum_s[(sp * 32 + lane) * 2 + ch] = rsum;
    __syncthreads();

    // O epilogue: LDTM, scale, smem transpose, coalesced STG
    {
        uint32_t o0[32], o1[32];
        LDTM32(o0, tmem + TM_O + ch * 64);
        LDTM32(o1, tmem + TM_O + ch * 64 + 32);
        asm volatile("tcgen05.wait::ld.sync.aligned;" ::: "memory");
        int row = sp * 32 + lane;
        float inv = 1.0f / (rsum_s[row * 2 + 0] + rsum_s[row * 2 + 1]);
        float* T = (float*)(smem + (db - sb)) + wid * (32 * 65);
#pragma unroll
        for (int j = 0; j < 32; j++) T[lane * 65 + j] = __uint_as_float(o0[j]) * inv;
#pragma unroll
        for (int j = 0; j < 32; j++) T[lane * 65 + 32 + j] = __uint_as_float(o1[j]) * inv;
        __syncwarp();
#pragma unroll
        for (int r = 0; r < 32; r++) {
            size_t o = (size_t)(m0 + sp * 32 + r) * N_DIM + h * D_DIM + ch * 64;
            out[o + lane] = T[r * 65 + lane];
            out[o + 32 + lane] = T[r * 65 + 32 + lane];
        }
    }
    __syncthreads();
    if (wid == 0) {
        asm volatile("tcgen05.dealloc.cta_group::1.sync.aligned.b32 %0, %1;"
                     :: "r"(tmem), "r"(512u));
    }
#endif
}

// ---------------------------------------------------------------------------
extern "C" void kernel_launch(void* const* d_in, const int* in_sizes, int n_in,
                              void* d_out, int out_size)
{
    const float* X = (const float*)d_in[0];
    const float* Wq = (const float*)d_in[1];
    const float* Wk = (const float*)d_in[2];
    const float* Wv = (const float*)d_in[3];
    const float* cK = (const float*)d_in[4];
    const float* cV = (const float*)d_in[5];
    float* out = (float*)d_out;

    cudaFuncSetAttribute(qkv_gemm_tc,
                         cudaFuncAttributeMaxDynamicSharedMemorySize, TC_SMEM);
    cudaFuncSetAttribute(attn_tc,
                         cudaFuncAttributeMaxDynamicSharedMemorySize, ATTN_SMEM);

    convert_x_kernel<<<2048, 256>>>(X);
    convert_w_kernel<<<dim3(64, 64, 3), 256>>>(Wq, Wk, Wv);
    qkv_gemm_tc<<<dim3(16, 8, 3), 256, TC_SMEM>>>();
    build_k_kernel<<<8192, 256>>>(cK);
    build_vt_kernel<<<dim3(64, 2, 32), 256>>>(cV);
    attn_tc<<<dim3(8, 32), 256, ATTN_SMEM>>>(out);
}